// round 2
// baseline (speedup 1.0000x reference)
#include <cuda_runtime.h>
#include <math.h>

// ---------------------------------------------------------------------------
// SuperGlue-style GNN: L=6 layers, D=128, H=4, DH=32, N=2048, B=1.
// x lives in d_out (desc0 at offset 0, desc1 at offset D*N). All scratch in
// __device__ globals. fp32 everywhere.
// ---------------------------------------------------------------------------

#define D_   128
#define N_   2048
#define L_   6
#define H_   4
#define C2_  256

__device__ float g_q   [2 * D_  * N_];
__device__ float g_k   [2 * D_  * N_];
__device__ float g_v   [2 * D_  * N_];
__device__ float g_msg [2 * D_  * N_];
__device__ float g_msg2[2 * D_  * N_];
__device__ float g_h   [2 * C2_ * N_];
__device__ float g_stats[2 * C2_ * 2];   // mean, rstd per (desc, channel)

// ---------------------------------------------------------------------------
// Batched GEMM:  Y[o][n] (+)= sum_i W[o][i] * X[i][n] + bias[o]
//   X rows < split come from X0, rows >= split from X1 (fused concat).
//   If stats != nullptr: X is transformed on load:  relu((x-mean)*rstd)
//   flags bit0: accumulate into Y (residual add).
// Tile: 64 (out) x 64 (n), K-step 16, 256 threads, 4x4 per thread.
// ---------------------------------------------------------------------------
struct GemmJob {
    const float* W;
    const float* bias;
    const float* X0;
    const float* X1;
    const float* stats;
    float*       Y;
    int IN;
    int split;
    int flags;
};
struct GemmBatch { GemmJob j[6]; };

__global__ __launch_bounds__(256) void gemm_kernel(GemmBatch batch)
{
    GemmJob jb = batch.j[blockIdx.z];
    const int IN = jb.IN;
    const int nb = blockIdx.x * 64;
    const int ob = blockIdx.y * 64;

    __shared__ float sW[16][68];   // [k][out]
    __shared__ float sX[16][68];   // [k][n]

    const int tid = threadIdx.x;
    const int tx  = tid & 15;      // n direction
    const int ty  = tid >> 4;      // out direction

    float acc[4][4];
#pragma unroll
    for (int i = 0; i < 4; i++)
#pragma unroll
        for (int j = 0; j < 4; j++) acc[i][j] = 0.f;

    for (int kb = 0; kb < IN; kb += 16) {
        // --- load W tile: 64 out x 16 k ---
        {
            int i  = tid * 4;
            int o  = i >> 4;        // 0..63
            int kk = i & 15;        // 0,4,8,12
            float4 w4 = *(const float4*)(jb.W + (size_t)(ob + o) * IN + kb + kk);
            sW[kk + 0][o] = w4.x;
            sW[kk + 1][o] = w4.y;
            sW[kk + 2][o] = w4.z;
            sW[kk + 3][o] = w4.w;
        }
        // --- load X tile: 16 k x 64 n ---
        {
            int i  = tid * 4;
            int kk = i >> 6;        // 0..15
            int nn = i & 63;
            int r  = kb + kk;
            const float* src = (r < jb.split) ? (jb.X0 + (size_t)r * N_)
                                              : (jb.X1 + (size_t)(r - jb.split) * N_);
            float4 xv = *(const float4*)(src + nb + nn);
            if (jb.stats) {
                float mean = jb.stats[2 * r];
                float rstd = jb.stats[2 * r + 1];
                xv.x = fmaxf(0.f, (xv.x - mean) * rstd);
                xv.y = fmaxf(0.f, (xv.y - mean) * rstd);
                xv.z = fmaxf(0.f, (xv.z - mean) * rstd);
                xv.w = fmaxf(0.f, (xv.w - mean) * rstd);
            }
            *(float4*)&sX[kk][nn] = xv;
        }
        __syncthreads();

#pragma unroll
        for (int kk = 0; kk < 16; kk++) {
            float4 a4 = *(const float4*)&sW[kk][ty * 4];
            float4 b4 = *(const float4*)&sX[kk][tx * 4];
            float a[4] = {a4.x, a4.y, a4.z, a4.w};
            float b[4] = {b4.x, b4.y, b4.z, b4.w};
#pragma unroll
            for (int i = 0; i < 4; i++)
#pragma unroll
                for (int j = 0; j < 4; j++) acc[i][j] += a[i] * b[j];
        }
        __syncthreads();
    }

    // --- epilogue ---
#pragma unroll
    for (int i = 0; i < 4; i++) {
        int o = ob + ty * 4 + i;
        float bias = jb.bias ? jb.bias[o] : 0.f;
        float* yp = jb.Y + (size_t)o * N_ + nb + tx * 4;
        float4 r;
        r.x = acc[i][0] + bias;
        r.y = acc[i][1] + bias;
        r.z = acc[i][2] + bias;
        r.w = acc[i][3] + bias;
        if (jb.flags & 1) {
            float4 old = *(const float4*)yp;
            r.x += old.x; r.y += old.y; r.z += old.z; r.w += old.w;
        }
        *(float4*)yp = r;
    }
}

// ---------------------------------------------------------------------------
// Fused multi-head attention (flash style, online softmax).
// Head h uses channels c = d*H + h (interleaved split from .reshape(b,DH,H,n)).
// Block: 256 threads = 8 warps; each warp owns 4 queries; lane l holds q_d /
// out_d for d = l. K/V tiles 32x32 in smem, shared by all warps.
// Grid: (2048/32, H, 2 descs)
// ---------------------------------------------------------------------------
__global__ __launch_bounds__(256) void attn_kernel(const float* __restrict__ gq,
                                                   const float* __restrict__ gk,
                                                   const float* __restrict__ gv,
                                                   float* __restrict__ gmsg)
{
    const int head = blockIdx.y;
    const int desc = blockIdx.z;
    const size_t base = (size_t)desc * D_ * N_;
    const float* q = gq + base;
    const float* k = gk + base;
    const float* v = gv + base;
    float* msg = gmsg + base;

    __shared__ float sK[32][33];
    __shared__ float sV[32][33];

    const int tid  = threadIdx.x;
    const int warp = tid >> 5;
    const int lane = tid & 31;
    const int n0   = blockIdx.x * 32 + warp * 4;   // 4 queries per warp

    // q: lane d holds q[(d*4+head)][n0+j]
    float qr[4];
#pragma unroll
    for (int j = 0; j < 4; j++)
        qr[j] = q[(size_t)(lane * H_ + head) * N_ + n0 + j];

    float M[4], S[4], O[4];
#pragma unroll
    for (int j = 0; j < 4; j++) { M[j] = -1e30f; S[j] = 0.f; O[j] = 0.f; }

    const float scale = 0.17677669529663687f;   // 1/sqrt(32)

    for (int mt = 0; mt < N_; mt += 32) {
        __syncthreads();
        // load K,V tile: 32 dims x 32 keys
        for (int i = tid; i < 32 * 32; i += 256) {
            int d = i >> 5, m = i & 31;
            size_t gidx = (size_t)(d * H_ + head) * N_ + mt + m;
            sK[d][m] = k[gidx];
            sV[d][m] = v[gidx];
        }
        __syncthreads();

        // scores: lane handles key m = mt + lane, for 4 queries
        float s[4] = {0.f, 0.f, 0.f, 0.f};
#pragma unroll
        for (int d = 0; d < 32; d++) {
            float kv = sK[d][lane];
#pragma unroll
            for (int j = 0; j < 4; j++)
                s[j] += __shfl_sync(0xffffffffu, qr[j], d) * kv;
        }

        float p[4];
#pragma unroll
        for (int j = 0; j < 4; j++) {
            s[j] *= scale;
            // tile max across lanes
            float tm = s[j];
#pragma unroll
            for (int off = 16; off > 0; off >>= 1)
                tm = fmaxf(tm, __shfl_xor_sync(0xffffffffu, tm, off));
            float newM = fmaxf(M[j], tm);
            float corr = __expf(M[j] - newM);
            O[j] *= corr;
            S[j] *= corr;
            M[j] = newM;
            p[j] = __expf(s[j] - newM);
            float ps = p[j];
#pragma unroll
            for (int off = 16; off > 0; off >>= 1)
                ps += __shfl_xor_sync(0xffffffffu, ps, off);
            S[j] += ps;
        }

        // accumulate output: out dim d = lane
#pragma unroll
        for (int jj = 0; jj < 32; jj++) {
            float vv = sV[lane][jj];
#pragma unroll
            for (int j = 0; j < 4; j++)
                O[j] += __shfl_sync(0xffffffffu, p[j], jj) * vv;
        }
    }

#pragma unroll
    for (int j = 0; j < 4; j++)
        msg[(size_t)(lane * H_ + head) * N_ + n0 + j] = O[j] / S[j];
}

// ---------------------------------------------------------------------------
// InstanceNorm1d stats: per (desc, channel), mean + rsqrt(var + eps) over N.
// Grid: (256 channels, 2 descs), block 256.
// ---------------------------------------------------------------------------
__global__ __launch_bounds__(256) void inorm_stats_kernel(const float* __restrict__ Hbuf,
                                                          float* __restrict__ stats)
{
    const int c  = blockIdx.x;
    const int dd = blockIdx.y;
    const float4* row = (const float4*)(Hbuf + ((size_t)dd * C2_ + c) * N_);

    float s = 0.f, ss = 0.f;
    for (int i = threadIdx.x; i < N_ / 4; i += 256) {
        float4 v = row[i];
        s  += v.x + v.y + v.z + v.w;
        ss += v.x * v.x + v.y * v.y + v.z * v.z + v.w * v.w;
    }
    // block reduce
    __shared__ float sh_s[8], sh_ss[8];
    for (int off = 16; off > 0; off >>= 1) {
        s  += __shfl_xor_sync(0xffffffffu, s,  off);
        ss += __shfl_xor_sync(0xffffffffu, ss, off);
    }
    int warp = threadIdx.x >> 5, lane = threadIdx.x & 31;
    if (lane == 0) { sh_s[warp] = s; sh_ss[warp] = ss; }
    __syncthreads();
    if (threadIdx.x == 0) {
        float ts = 0.f, tss = 0.f;
        for (int w = 0; w < 8; w++) { ts += sh_s[w]; tss += sh_ss[w]; }
        float mean = ts * (1.f / N_);
        float var  = tss * (1.f / N_) - mean * mean;
        var = fmaxf(var, 0.f);
        stats[((size_t)dd * C2_ + c) * 2 + 0] = mean;
        stats[((size_t)dd * C2_ + c) * 2 + 1] = rsqrtf(var + 1e-5f);
    }
}

// ---------------------------------------------------------------------------
// Init: copy desc0 || desc1 into d_out (x buffer).
// ---------------------------------------------------------------------------
__global__ __launch_bounds__(256) void init_kernel(const float* __restrict__ a,
                                                   const float* __restrict__ b,
                                                   float* __restrict__ out)
{
    int i = blockIdx.x * blockDim.x + threadIdx.x;   // 0 .. 131071 (float4s)
    const int n4 = D_ * N_ / 4;
    float4* o = (float4*)out;
    if (i < n4)           o[i] = ((const float4*)a)[i];
    else if (i < 2 * n4)  o[i] = ((const float4*)b)[i - n4];
}

// ---------------------------------------------------------------------------
// Host launcher
// ---------------------------------------------------------------------------
extern "C" void kernel_launch(void* const* d_in, const int* in_sizes, int n_in,
                              void* d_out, int out_size)
{
    const float* desc0 = (const float*)d_in[0];
    const float* desc1 = (const float*)d_in[1];
    const float* Wq = (const float*)d_in[2];
    const float* bq = (const float*)d_in[3];
    const float* Wk = (const float*)d_in[4];
    const float* bk = (const float*)d_in[5];
    const float* Wv = (const float*)d_in[6];
    const float* bv = (const float*)d_in[7];
    const float* Wm = (const float*)d_in[8];
    const float* bm = (const float*)d_in[9];
    const float* W1 = (const float*)d_in[10];
    const float* b1 = (const float*)d_in[11];
    const float* W2 = (const float*)d_in[12];
    const float* b2 = (const float*)d_in[13];

    float* x  = (float*)d_out;
    float* x0 = x;
    float* x1 = x + (size_t)D_ * N_;

    float *p_q, *p_k, *p_v, *p_msg, *p_msg2, *p_h, *p_stats;
    cudaGetSymbolAddress((void**)&p_q,     g_q);
    cudaGetSymbolAddress((void**)&p_k,     g_k);
    cudaGetSymbolAddress((void**)&p_v,     g_v);
    cudaGetSymbolAddress((void**)&p_msg,   g_msg);
    cudaGetSymbolAddress((void**)&p_msg2,  g_msg2);
    cudaGetSymbolAddress((void**)&p_h,     g_h);
    cudaGetSymbolAddress((void**)&p_stats, g_stats);

    const int BIG = 1 << 30;

    init_kernel<<<512, 256>>>(desc0, desc1, x);

    for (int l = 0; l < L_; l++) {
        const bool cross = (l & 1);
        const float* s0 = cross ? x1 : x0;
        const float* s1 = cross ? x0 : x1;

        const float* Wq_l = Wq + (size_t)l * D_ * D_;
        const float* bq_l = bq + (size_t)l * D_;
        const float* Wk_l = Wk + (size_t)l * D_ * D_;
        const float* bk_l = bk + (size_t)l * D_;
        const float* Wv_l = Wv + (size_t)l * D_ * D_;
        const float* bv_l = bv + (size_t)l * D_;
        const float* Wm_l = Wm + (size_t)l * D_ * D_;
        const float* bm_l = bm + (size_t)l * D_;
        const float* W1_l = W1 + (size_t)l * C2_ * C2_;
        const float* b1_l = b1 + (size_t)l * C2_;
        const float* W2_l = W2 + (size_t)l * D_ * C2_;
        const float* b2_l = b2 + (size_t)l * D_;

        // ---- Q/K/V projections (6 jobs: both descs) ----
        GemmBatch bqkv{};
        bqkv.j[0] = {Wq_l, bq_l, x0, nullptr, nullptr, p_q,             D_, BIG, 0};
        bqkv.j[1] = {Wq_l, bq_l, x1, nullptr, nullptr, p_q + D_ * N_,   D_, BIG, 0};
        bqkv.j[2] = {Wk_l, bk_l, s0, nullptr, nullptr, p_k,             D_, BIG, 0};
        bqkv.j[3] = {Wk_l, bk_l, s1, nullptr, nullptr, p_k + D_ * N_,   D_, BIG, 0};
        bqkv.j[4] = {Wv_l, bv_l, s0, nullptr, nullptr, p_v,             D_, BIG, 0};
        bqkv.j[5] = {Wv_l, bv_l, s1, nullptr, nullptr, p_v + D_ * N_,   D_, BIG, 0};
        gemm_kernel<<<dim3(N_ / 64, D_ / 64, 6), 256>>>(bqkv);

        // ---- attention (both descs, 4 heads) ----
        attn_kernel<<<dim3(N_ / 32, H_, 2), 256>>>(p_q, p_k, p_v, p_msg);

        // ---- message projection Wm ----
        GemmBatch bmsg{};
        bmsg.j[0] = {Wm_l, bm_l, p_msg,           nullptr, nullptr, p_msg2,           D_, BIG, 0};
        bmsg.j[1] = {Wm_l, bm_l, p_msg + D_ * N_, nullptr, nullptr, p_msg2 + D_ * N_, D_, BIG, 0};
        gemm_kernel<<<dim3(N_ / 64, D_ / 64, 2), 256>>>(bmsg);

        // ---- MLP layer 1: h = W1 * concat([x, msg2]) + b1 ----
        GemmBatch bmlp1{};
        bmlp1.j[0] = {W1_l, b1_l, x0, p_msg2,           nullptr, p_h,             C2_, D_, 0};
        bmlp1.j[1] = {W1_l, b1_l, x1, p_msg2 + D_ * N_, nullptr, p_h + C2_ * N_,  C2_, D_, 0};
        gemm_kernel<<<dim3(N_ / 64, C2_ / 64, 2), 256>>>(bmlp1);

        // ---- InstanceNorm stats ----
        inorm_stats_kernel<<<dim3(C2_, 2), 256>>>(p_h, p_stats);

        // ---- MLP layer 2 (norm+relu fused on load) + residual add into x ----
        GemmBatch bmlp2{};
        bmlp2.j[0] = {W2_l, b2_l, p_h,            nullptr, p_stats,            x0, C2_, BIG, 1};
        bmlp2.j[1] = {W2_l, b2_l, p_h + C2_ * N_, nullptr, p_stats + C2_ * 2,  x1, C2_, BIG, 1};
        gemm_kernel<<<dim3(N_ / 64, D_ / 64, 2), 256>>>(bmlp2);
    }
}

// round 3
// speedup vs baseline: 1.9749x; 1.9749x over previous
#include <cuda_runtime.h>
#include <math.h>

// ---------------------------------------------------------------------------
// SuperGlue-style GNN: L=6 layers, D=128, H=4, DH=32, N=2048, B=1.
// x lives in d_out (desc0 at offset 0, desc1 at offset D*N). All scratch in
// __device__ globals. fp32 everywhere.
// ---------------------------------------------------------------------------

#define D_   128
#define N_   2048
#define L_   6
#define H_   4
#define C2_  256

__device__ float g_q   [2 * D_  * N_];
__device__ float g_k   [2 * D_  * N_];
__device__ float g_v   [2 * D_  * N_];
__device__ float g_msg [2 * D_  * N_];
__device__ float g_msg2[2 * D_  * N_];
__device__ float g_h   [2 * C2_ * N_];
__device__ float g_stats[2 * C2_ * 2];   // mean, rstd per (desc, channel)

// ---------------------------------------------------------------------------
// Batched GEMM:  Y[o][n] (+)= sum_i W[o][i] * X[i][n] + bias[o]
//   X rows < split come from X0, rows >= split from X1 (fused concat).
//   If stats != nullptr: X is transformed on load:  relu((x-mean)*rstd)
//   flags bit0: accumulate into Y (residual add).
// Tile: 64 (out) x 64 (n), K-step 16, 256 threads, 4x4 per thread.
// ---------------------------------------------------------------------------
struct GemmJob {
    const float* W;
    const float* bias;
    const float* X0;
    const float* X1;
    const float* stats;
    float*       Y;
    int IN;
    int split;
    int flags;
};
struct GemmBatch { GemmJob j[6]; };

__global__ __launch_bounds__(256) void gemm_kernel(GemmBatch batch)
{
    GemmJob jb = batch.j[blockIdx.z];
    const int IN = jb.IN;
    const int nb = blockIdx.x * 64;
    const int ob = blockIdx.y * 64;

    __shared__ float sW[16][68];   // [k][out]
    __shared__ float sX[16][68];   // [k][n]

    const int tid = threadIdx.x;
    const int tx  = tid & 15;      // n direction
    const int ty  = tid >> 4;      // out direction

    float acc[4][4];
#pragma unroll
    for (int i = 0; i < 4; i++)
#pragma unroll
        for (int j = 0; j < 4; j++) acc[i][j] = 0.f;

    for (int kb = 0; kb < IN; kb += 16) {
        // --- load W tile: 64 out x 16 k ---
        {
            int i  = tid * 4;
            int o  = i >> 4;        // 0..63
            int kk = i & 15;        // 0,4,8,12
            float4 w4 = *(const float4*)(jb.W + (size_t)(ob + o) * IN + kb + kk);
            sW[kk + 0][o] = w4.x;
            sW[kk + 1][o] = w4.y;
            sW[kk + 2][o] = w4.z;
            sW[kk + 3][o] = w4.w;
        }
        // --- load X tile: 16 k x 64 n ---
        {
            int i  = tid * 4;
            int kk = i >> 6;        // 0..15
            int nn = i & 63;
            int r  = kb + kk;
            const float* src = (r < jb.split) ? (jb.X0 + (size_t)r * N_)
                                              : (jb.X1 + (size_t)(r - jb.split) * N_);
            float4 xv = *(const float4*)(src + nb + nn);
            if (jb.stats) {
                float mean = jb.stats[2 * r];
                float rstd = jb.stats[2 * r + 1];
                xv.x = fmaxf(0.f, (xv.x - mean) * rstd);
                xv.y = fmaxf(0.f, (xv.y - mean) * rstd);
                xv.z = fmaxf(0.f, (xv.z - mean) * rstd);
                xv.w = fmaxf(0.f, (xv.w - mean) * rstd);
            }
            *(float4*)&sX[kk][nn] = xv;
        }
        __syncthreads();

#pragma unroll
        for (int kk = 0; kk < 16; kk++) {
            float4 a4 = *(const float4*)&sW[kk][ty * 4];
            float4 b4 = *(const float4*)&sX[kk][tx * 4];
            float a[4] = {a4.x, a4.y, a4.z, a4.w};
            float b[4] = {b4.x, b4.y, b4.z, b4.w};
#pragma unroll
            for (int i = 0; i < 4; i++)
#pragma unroll
                for (int j = 0; j < 4; j++) acc[i][j] += a[i] * b[j];
        }
        __syncthreads();
    }

    // --- epilogue ---
#pragma unroll
    for (int i = 0; i < 4; i++) {
        int o = ob + ty * 4 + i;
        float bias = jb.bias ? jb.bias[o] : 0.f;
        float* yp = jb.Y + (size_t)o * N_ + nb + tx * 4;
        float4 r;
        r.x = acc[i][0] + bias;
        r.y = acc[i][1] + bias;
        r.z = acc[i][2] + bias;
        r.w = acc[i][3] + bias;
        if (jb.flags & 1) {
            float4 old = *(const float4*)yp;
            r.x += old.x; r.y += old.y; r.z += old.z; r.w += old.w;
        }
        *(float4*)yp = r;
    }
}

// ---------------------------------------------------------------------------
// Fused flash attention, register-tiled FFMA version (no shuffles in hot loop).
// Head h uses channels c = d*H + h (interleaved from .reshape(b,DH,H,n)).
// Block: 256 threads; 64 queries of one (head, desc). Keys tiled by 64.
// S-phase: thread (ty=q-group, tx=k-group) computes 4x4 scores over DH=32.
// Softmax: per-row reduce via 4 xor-shuffles within the 16-lane tx group.
// O-phase: thread (td=dim-pair, tq=q-group) accumulates O[2][4] from sVT x sP.
// Grid: (N/64, H, 2)
// ---------------------------------------------------------------------------
__global__ __launch_bounds__(256) void attn_kernel(const float* __restrict__ gq,
                                                   const float* __restrict__ gk,
                                                   const float* __restrict__ gv,
                                                   float* __restrict__ gmsg)
{
    const int head = blockIdx.y;
    const int desc = blockIdx.z;
    const size_t base = (size_t)desc * D_ * N_;
    const float* q = gq + base;
    const float* k = gk + base;
    const float* v = gv + base;
    float* msg = gmsg + base;

    __shared__ float sQ [32][68];   // [d][q]   (prescaled by 1/sqrt(32))
    __shared__ float sK [32][68];   // [d][m]
    __shared__ float sVT[64][34];   // [m][d]
    __shared__ float sP [64][68];   // [m][q]
    __shared__ float sRow[64];      // per-query corr (per tile), then L (final)

    const int tid = threadIdx.x;
    const int ty  = tid >> 4;       // S-phase: query group   | O-phase: dim pair
    const int tx  = tid & 15;       // S-phase: key group     | O-phase: q group
    const int q0  = blockIdx.x * 64;

    // ---- load Q tile (32 dims x 64 queries), prescaled ----
    {
        const float scale = 0.17677669529663687f;   // 1/sqrt(32)
#pragma unroll
        for (int r = 0; r < 2; r++) {
            int lin = tid + r * 256;        // 0..511 float4 slots
            int d   = lin >> 4;             // 0..31
            int m4  = (lin & 15) * 4;       // 0..60
            float4 x = *(const float4*)(q + (size_t)(d * H_ + head) * N_ + q0 + m4);
            x.x *= scale; x.y *= scale; x.z *= scale; x.w *= scale;
            *(float4*)&sQ[d][m4] = x;
        }
    }

    float M[4], Lsum[4];
    float O[2][4];
#pragma unroll
    for (int i = 0; i < 4; i++) { M[i] = -1e30f; Lsum[i] = 0.f; }
#pragma unroll
    for (int d = 0; d < 2; d++)
#pragma unroll
        for (int j = 0; j < 4; j++) O[d][j] = 0.f;

    for (int mt = 0; mt < N_; mt += 64) {
        __syncthreads();   // protect sK/sVT/sP/sRow from previous iteration
        // ---- load K and V tiles ----
#pragma unroll
        for (int r = 0; r < 2; r++) {
            int lin = tid + r * 256;
            int d   = lin >> 4;
            int m4  = (lin & 15) * 4;
            size_t g = (size_t)(d * H_ + head) * N_ + mt + m4;
            *(float4*)&sK[d][m4] = *(const float4*)(k + g);
            float4 vv = *(const float4*)(v + g);
            sVT[m4 + 0][d] = vv.x;
            sVT[m4 + 1][d] = vv.y;
            sVT[m4 + 2][d] = vv.z;
            sVT[m4 + 3][d] = vv.w;
        }
        __syncthreads();

        // ---- S-phase: 4x4 score microtile over 32 dims ----
        float acc[4][4];
#pragma unroll
        for (int i = 0; i < 4; i++)
#pragma unroll
            for (int j = 0; j < 4; j++) acc[i][j] = 0.f;
#pragma unroll
        for (int d = 0; d < 32; d++) {
            float4 a4 = *(const float4*)&sQ[d][ty * 4];
            float4 b4 = *(const float4*)&sK[d][tx * 4];
            float a[4] = {a4.x, a4.y, a4.z, a4.w};
            float b[4] = {b4.x, b4.y, b4.z, b4.w};
#pragma unroll
            for (int i = 0; i < 4; i++)
#pragma unroll
                for (int j = 0; j < 4; j++) acc[i][j] += a[i] * b[j];
        }

        // ---- online softmax (row reduce across the 16 tx lanes) ----
        float p[4][4];
#pragma unroll
        for (int i = 0; i < 4; i++) {
            float tm = fmaxf(fmaxf(acc[i][0], acc[i][1]), fmaxf(acc[i][2], acc[i][3]));
#pragma unroll
            for (int off = 8; off > 0; off >>= 1)
                tm = fmaxf(tm, __shfl_xor_sync(0xffffffffu, tm, off));
            float newM = fmaxf(M[i], tm);
            float corr = __expf(M[i] - newM);
            M[i] = newM;
            float ls = 0.f;
#pragma unroll
            for (int j = 0; j < 4; j++) {
                p[i][j] = __expf(acc[i][j] - newM);
                ls += p[i][j];
            }
#pragma unroll
            for (int off = 8; off > 0; off >>= 1)
                ls += __shfl_xor_sync(0xffffffffu, ls, off);
            Lsum[i] = Lsum[i] * corr + ls;
            if (tx == 0) sRow[ty * 4 + i] = corr;
        }

        // ---- write P tile: sP[m][q] ----
#pragma unroll
        for (int j = 0; j < 4; j++) {
            float4 pv = make_float4(p[0][j], p[1][j], p[2][j], p[3][j]);
            *(float4*)&sP[tx * 4 + j][ty * 4] = pv;
        }
        __syncthreads();

        // ---- O-phase: ty -> dim pair, tx -> q group ----
        {
            float4 c4 = *(const float4*)&sRow[tx * 4];
            float c[4] = {c4.x, c4.y, c4.z, c4.w};
#pragma unroll
            for (int d = 0; d < 2; d++)
#pragma unroll
                for (int j = 0; j < 4; j++) O[d][j] *= c[j];
#pragma unroll
            for (int m = 0; m < 64; m++) {
                float2 a2 = *(const float2*)&sVT[m][ty * 2];
                float4 b4 = *(const float4*)&sP[m][tx * 4];
                O[0][0] += a2.x * b4.x;  O[0][1] += a2.x * b4.y;
                O[0][2] += a2.x * b4.z;  O[0][3] += a2.x * b4.w;
                O[1][0] += a2.y * b4.x;  O[1][1] += a2.y * b4.y;
                O[1][2] += a2.y * b4.z;  O[1][3] += a2.y * b4.w;
            }
        }
    }

    __syncthreads();
    if (tx == 0) {
#pragma unroll
        for (int i = 0; i < 4; i++) sRow[ty * 4 + i] = Lsum[i];
    }
    __syncthreads();

    {
        float4 l4 = *(const float4*)&sRow[tx * 4];
        float rl[4] = {1.f / l4.x, 1.f / l4.y, 1.f / l4.z, 1.f / l4.w};
#pragma unroll
        for (int d = 0; d < 2; d++) {
            int ch = (ty * 2 + d) * H_ + head;
            float4 o4 = make_float4(O[d][0] * rl[0], O[d][1] * rl[1],
                                    O[d][2] * rl[2], O[d][3] * rl[3]);
            *(float4*)(msg + (size_t)ch * N_ + q0 + tx * 4) = o4;
        }
    }
}

// ---------------------------------------------------------------------------
// InstanceNorm1d stats: per (desc, channel), mean + rsqrt(var + eps) over N.
// Grid: (256 channels, 2 descs), block 256.
// ---------------------------------------------------------------------------
__global__ __launch_bounds__(256) void inorm_stats_kernel(const float* __restrict__ Hbuf,
                                                          float* __restrict__ stats)
{
    const int c  = blockIdx.x;
    const int dd = blockIdx.y;
    const float4* row = (const float4*)(Hbuf + ((size_t)dd * C2_ + c) * N_);

    float s = 0.f, ss = 0.f;
    for (int i = threadIdx.x; i < N_ / 4; i += 256) {
        float4 v = row[i];
        s  += v.x + v.y + v.z + v.w;
        ss += v.x * v.x + v.y * v.y + v.z * v.z + v.w * v.w;
    }
    __shared__ float sh_s[8], sh_ss[8];
    for (int off = 16; off > 0; off >>= 1) {
        s  += __shfl_xor_sync(0xffffffffu, s,  off);
        ss += __shfl_xor_sync(0xffffffffu, ss, off);
    }
    int warp = threadIdx.x >> 5, lane = threadIdx.x & 31;
    if (lane == 0) { sh_s[warp] = s; sh_ss[warp] = ss; }
    __syncthreads();
    if (threadIdx.x == 0) {
        float ts = 0.f, tss = 0.f;
        for (int w = 0; w < 8; w++) { ts += sh_s[w]; tss += sh_ss[w]; }
        float mean = ts * (1.f / N_);
        float var  = tss * (1.f / N_) - mean * mean;
        var = fmaxf(var, 0.f);
        stats[((size_t)dd * C2_ + c) * 2 + 0] = mean;
        stats[((size_t)dd * C2_ + c) * 2 + 1] = rsqrtf(var + 1e-5f);
    }
}

// ---------------------------------------------------------------------------
// Init: copy desc0 || desc1 into d_out (x buffer).
// ---------------------------------------------------------------------------
__global__ __launch_bounds__(256) void init_kernel(const float* __restrict__ a,
                                                   const float* __restrict__ b,
                                                   float* __restrict__ out)
{
    int i = blockIdx.x * blockDim.x + threadIdx.x;
    const int n4 = D_ * N_ / 4;
    float4* o = (float4*)out;
    if (i < n4)           o[i] = ((const float4*)a)[i];
    else if (i < 2 * n4)  o[i] = ((const float4*)b)[i - n4];
}

// ---------------------------------------------------------------------------
// Host launcher
// ---------------------------------------------------------------------------
extern "C" void kernel_launch(void* const* d_in, const int* in_sizes, int n_in,
                              void* d_out, int out_size)
{
    const float* desc0 = (const float*)d_in[0];
    const float* desc1 = (const float*)d_in[1];
    const float* Wq = (const float*)d_in[2];
    const float* bq = (const float*)d_in[3];
    const float* Wk = (const float*)d_in[4];
    const float* bk = (const float*)d_in[5];
    const float* Wv = (const float*)d_in[6];
    const float* bv = (const float*)d_in[7];
    const float* Wm = (const float*)d_in[8];
    const float* bm = (const float*)d_in[9];
    const float* W1 = (const float*)d_in[10];
    const float* b1 = (const float*)d_in[11];
    const float* W2 = (const float*)d_in[12];
    const float* b2 = (const float*)d_in[13];

    float* x  = (float*)d_out;
    float* x0 = x;
    float* x1 = x + (size_t)D_ * N_;

    float *p_q, *p_k, *p_v, *p_msg, *p_msg2, *p_h, *p_stats;
    cudaGetSymbolAddress((void**)&p_q,     g_q);
    cudaGetSymbolAddress((void**)&p_k,     g_k);
    cudaGetSymbolAddress((void**)&p_v,     g_v);
    cudaGetSymbolAddress((void**)&p_msg,   g_msg);
    cudaGetSymbolAddress((void**)&p_msg2,  g_msg2);
    cudaGetSymbolAddress((void**)&p_h,     g_h);
    cudaGetSymbolAddress((void**)&p_stats, g_stats);

    const int BIG = 1 << 30;

    init_kernel<<<512, 256>>>(desc0, desc1, x);

    for (int l = 0; l < L_; l++) {
        const bool cross = (l & 1);
        const float* s0 = cross ? x1 : x0;
        const float* s1 = cross ? x0 : x1;

        const float* Wq_l = Wq + (size_t)l * D_ * D_;
        const float* bq_l = bq + (size_t)l * D_;
        const float* Wk_l = Wk + (size_t)l * D_ * D_;
        const float* bk_l = bk + (size_t)l * D_;
        const float* Wv_l = Wv + (size_t)l * D_ * D_;
        const float* bv_l = bv + (size_t)l * D_;
        const float* Wm_l = Wm + (size_t)l * D_ * D_;
        const float* bm_l = bm + (size_t)l * D_;
        const float* W1_l = W1 + (size_t)l * C2_ * C2_;
        const float* b1_l = b1 + (size_t)l * C2_;
        const float* W2_l = W2 + (size_t)l * D_ * C2_;
        const float* b2_l = b2 + (size_t)l * D_;

        // ---- Q/K/V projections (6 jobs: both descs) ----
        GemmBatch bqkv{};
        bqkv.j[0] = {Wq_l, bq_l, x0, nullptr, nullptr, p_q,             D_, BIG, 0};
        bqkv.j[1] = {Wq_l, bq_l, x1, nullptr, nullptr, p_q + D_ * N_,   D_, BIG, 0};
        bqkv.j[2] = {Wk_l, bk_l, s0, nullptr, nullptr, p_k,             D_, BIG, 0};
        bqkv.j[3] = {Wk_l, bk_l, s1, nullptr, nullptr, p_k + D_ * N_,   D_, BIG, 0};
        bqkv.j[4] = {Wv_l, bv_l, s0, nullptr, nullptr, p_v,             D_, BIG, 0};
        bqkv.j[5] = {Wv_l, bv_l, s1, nullptr, nullptr, p_v + D_ * N_,   D_, BIG, 0};
        gemm_kernel<<<dim3(N_ / 64, D_ / 64, 6), 256>>>(bqkv);

        // ---- attention (both descs, 4 heads) ----
        attn_kernel<<<dim3(N_ / 64, H_, 2), 256>>>(p_q, p_k, p_v, p_msg);

        // ---- message projection Wm ----
        GemmBatch bmsg{};
        bmsg.j[0] = {Wm_l, bm_l, p_msg,           nullptr, nullptr, p_msg2,           D_, BIG, 0};
        bmsg.j[1] = {Wm_l, bm_l, p_msg + D_ * N_, nullptr, nullptr, p_msg2 + D_ * N_, D_, BIG, 0};
        gemm_kernel<<<dim3(N_ / 64, D_ / 64, 2), 256>>>(bmsg);

        // ---- MLP layer 1: h = W1 * concat([x, msg2]) + b1 ----
        GemmBatch bmlp1{};
        bmlp1.j[0] = {W1_l, b1_l, x0, p_msg2,           nullptr, p_h,             C2_, D_, 0};
        bmlp1.j[1] = {W1_l, b1_l, x1, p_msg2 + D_ * N_, nullptr, p_h + C2_ * N_,  C2_, D_, 0};
        gemm_kernel<<<dim3(N_ / 64, C2_ / 64, 2), 256>>>(bmlp1);

        // ---- InstanceNorm stats ----
        inorm_stats_kernel<<<dim3(C2_, 2), 256>>>(p_h, p_stats);

        // ---- MLP layer 2 (norm+relu fused on load) + residual add into x ----
        GemmBatch bmlp2{};
        bmlp2.j[0] = {W2_l, b2_l, p_h,            nullptr, p_stats,            x0, C2_, BIG, 1};
        bmlp2.j[1] = {W2_l, b2_l, p_h + C2_ * N_, nullptr, p_stats + C2_ * 2,  x1, C2_, BIG, 1};
        gemm_kernel<<<dim3(N_ / 64, D_ / 64, 2), 256>>>(bmlp2);
    }
}

// round 7
// speedup vs baseline: 2.0645x; 1.0454x over previous
#include <cuda_runtime.h>
#include <cstdint>
#include <math.h>

// ---------------------------------------------------------------------------
// SuperGlue-style GNN: L=6 layers, D=128, H=4, DH=32, N=2048, B=1.
// GEMMs on mma.sync tf32 tensor cores (sm_103-portable); attention FFMA.
// ---------------------------------------------------------------------------

#define D_   128
#define N_   2048
#define L_   6
#define H_   4
#define C2_  256

__device__ float g_q   [2 * D_  * N_];
__device__ float g_k   [2 * D_  * N_];
__device__ float g_v   [2 * D_  * N_];
__device__ float g_msg [2 * D_  * N_];
__device__ float g_msg2[2 * D_  * N_];
__device__ float g_h   [2 * C2_ * N_];
__device__ float g_stats[2 * C2_ * 2];

__device__ __forceinline__ uint32_t f2tf32(float x) {
    uint32_t r;
    asm("cvt.rna.tf32.f32 %0, %1;" : "=r"(r) : "f"(x));
    return r;
}

__device__ __forceinline__ void mma_tf32(float* d, const uint32_t* a, const uint32_t* b) {
    asm volatile(
        "mma.sync.aligned.m16n8k8.row.col.f32.tf32.tf32.f32 "
        "{%0,%1,%2,%3}, {%4,%5,%6,%7}, {%8,%9}, {%0,%1,%2,%3};"
        : "+f"(d[0]), "+f"(d[1]), "+f"(d[2]), "+f"(d[3])
        : "r"(a[0]), "r"(a[1]), "r"(a[2]), "r"(a[3]), "r"(b[0]), "r"(b[1]));
}

// ---------------------------------------------------------------------------
// Batched GEMM (tensor cores):  Y[o][n] (+)= sum_k W[o][k] X[k][n] + bias[o]
//   X rows < split from X0 else X1 (fused concat); stats => relu((x-m)*rstd)
//   flags bit0: accumulate into Y (residual).
// CTA 128(out) x 128(n), 256 thr = 8 warps (2 M x 4 N), warp tile 64x32.
// K-chunks of 32, 4 k-steps of 8 via m16n8k8 tf32.
// ---------------------------------------------------------------------------
struct GemmJob {
    const float* W;
    const float* bias;
    const float* X0;
    const float* X1;
    const float* stats;
    float*       Y;
    int IN;
    int split;
    int flags;
};
struct GemmBatch { GemmJob j[6]; };

#define SA_STRIDE 36
#define SB_STRIDE 136

__global__ __launch_bounds__(256) void gemm_mma_kernel(GemmBatch batch)
{
    GemmJob jb = batch.j[blockIdx.z];
    const int IN = jb.IN;
    const int KT = IN >> 5;
    const int nb = blockIdx.x * 128;
    const int ob = blockIdx.y * 128;

    __shared__ uint32_t sA[128 * SA_STRIDE];   // [m][k] tf32 bits
    __shared__ uint32_t sB[32 * SB_STRIDE];    // [k][n] tf32 bits

    const int tid  = threadIdx.x;
    const int wid  = tid >> 5;
    const int lane = tid & 31;
    const int g    = lane >> 2;      // group id 0..7
    const int c    = lane & 3;       // thread-in-group 0..3
    const int wm   = wid & 1;        // M half (64)
    const int wn   = wid >> 1;       // N quarter (32)

    float d[4][4][4];
#pragma unroll
    for (int mi = 0; mi < 4; mi++)
#pragma unroll
        for (int ni = 0; ni < 4; ni++)
#pragma unroll
            for (int r = 0; r < 4; r++) d[mi][ni][r] = 0.f;

    for (int kt = 0; kt < KT; kt++) {
        const int k0 = kt * 32;

        // ---- load A tile: W[ob..+127][k0..+31] -> sA[m][k] ----
#pragma unroll
        for (int p = 0; p < 4; p++) {
            int lin = tid + p * 256;
            int o   = lin >> 3;
            int kq  = lin & 7;
            float4 w = *(const float4*)(jb.W + (size_t)(ob + o) * IN + k0 + kq * 4);
            uint4 t = make_uint4(f2tf32(w.x), f2tf32(w.y), f2tf32(w.z), f2tf32(w.w));
            *(uint4*)&sA[o * SA_STRIDE + kq * 4] = t;
        }
        // ---- load B tile: X[k0..+31][nb..+127] -> sB[k][n] (fused ops) ----
#pragma unroll
        for (int p = 0; p < 4; p++) {
            int lin = tid + p * 256;
            int kk  = lin >> 5;
            int ng  = lin & 31;
            int r   = k0 + kk;
            const float* src = (r < jb.split) ? (jb.X0 + (size_t)r * N_)
                                              : (jb.X1 + (size_t)(r - jb.split) * N_);
            float4 xv = *(const float4*)(src + nb + ng * 4);
            if (jb.stats) {
                float mean = jb.stats[2 * r];
                float rstd = jb.stats[2 * r + 1];
                xv.x = fmaxf(0.f, (xv.x - mean) * rstd);
                xv.y = fmaxf(0.f, (xv.y - mean) * rstd);
                xv.z = fmaxf(0.f, (xv.z - mean) * rstd);
                xv.w = fmaxf(0.f, (xv.w - mean) * rstd);
            }
            uint4 t = make_uint4(f2tf32(xv.x), f2tf32(xv.y), f2tf32(xv.z), f2tf32(xv.w));
            *(uint4*)&sB[kk * SB_STRIDE + ng * 4] = t;
        }
        __syncthreads();

#pragma unroll
        for (int ks = 0; ks < 4; ks++) {
            uint32_t a[4][4];
#pragma unroll
            for (int mi = 0; mi < 4; mi++) {
                int row = wm * 64 + mi * 16;
                int kc  = ks * 8 + c;
                a[mi][0] = sA[(row + g)     * SA_STRIDE + kc];
                a[mi][1] = sA[(row + g + 8) * SA_STRIDE + kc];
                a[mi][2] = sA[(row + g)     * SA_STRIDE + kc + 4];
                a[mi][3] = sA[(row + g + 8) * SA_STRIDE + kc + 4];
            }
            uint32_t b[4][2];
#pragma unroll
            for (int ni = 0; ni < 4; ni++) {
                int col = wn * 32 + ni * 8 + g;
                b[ni][0] = sB[(ks * 8 + c)     * SB_STRIDE + col];
                b[ni][1] = sB[(ks * 8 + c + 4) * SB_STRIDE + col];
            }
#pragma unroll
            for (int mi = 0; mi < 4; mi++)
#pragma unroll
                for (int ni = 0; ni < 4; ni++)
                    mma_tf32(d[mi][ni], a[mi], b[ni]);
        }
        __syncthreads();
    }

    // ---- epilogue: bias + optional residual, fp32 store ----
#pragma unroll
    for (int mi = 0; mi < 4; mi++) {
        int orow = ob + wm * 64 + mi * 16 + g;
        float bias0 = jb.bias ? jb.bias[orow]     : 0.f;
        float bias1 = jb.bias ? jb.bias[orow + 8] : 0.f;
        float* y0 = jb.Y + (size_t)orow * N_;
        float* y1 = jb.Y + (size_t)(orow + 8) * N_;
#pragma unroll
        for (int ni = 0; ni < 4; ni++) {
            int ncol = nb + wn * 32 + ni * 8 + c * 2;
            float2 v0 = make_float2(d[mi][ni][0] + bias0, d[mi][ni][1] + bias0);
            float2 v1 = make_float2(d[mi][ni][2] + bias1, d[mi][ni][3] + bias1);
            if (jb.flags & 1) {
                float2 o0 = *(const float2*)(y0 + ncol);
                float2 o1 = *(const float2*)(y1 + ncol);
                v0.x += o0.x; v0.y += o0.y;
                v1.x += o1.x; v1.y += o1.y;
            }
            *(float2*)(y0 + ncol) = v0;
            *(float2*)(y1 + ncol) = v1;
        }
    }
}

// ---------------------------------------------------------------------------
// Fused flash attention, register-tiled FFMA (unchanged, proven).
// ---------------------------------------------------------------------------
__global__ __launch_bounds__(256) void attn_kernel(const float* __restrict__ gq,
                                                   const float* __restrict__ gk,
                                                   const float* __restrict__ gv,
                                                   float* __restrict__ gmsg)
{
    const int head = blockIdx.y;
    const int desc = blockIdx.z;
    const size_t base = (size_t)desc * D_ * N_;
    const float* q = gq + base;
    const float* k = gk + base;
    const float* v = gv + base;
    float* msg = gmsg + base;

    __shared__ float sQ [32][68];
    __shared__ float sK [32][68];
    __shared__ float sVT[64][34];
    __shared__ float sP [64][68];
    __shared__ float sRow[64];

    const int tid = threadIdx.x;
    const int ty  = tid >> 4;
    const int tx  = tid & 15;
    const int q0  = blockIdx.x * 64;

    {
        const float scale = 0.17677669529663687f;
#pragma unroll
        for (int r = 0; r < 2; r++) {
            int lin = tid + r * 256;
            int d   = lin >> 4;
            int m4  = (lin & 15) * 4;
            float4 x = *(const float4*)(q + (size_t)(d * H_ + head) * N_ + q0 + m4);
            x.x *= scale; x.y *= scale; x.z *= scale; x.w *= scale;
            *(float4*)&sQ[d][m4] = x;
        }
    }

    float M[4], Lsum[4];
    float O[2][4];
#pragma unroll
    for (int i = 0; i < 4; i++) { M[i] = -1e30f; Lsum[i] = 0.f; }
#pragma unroll
    for (int d = 0; d < 2; d++)
#pragma unroll
        for (int j = 0; j < 4; j++) O[d][j] = 0.f;

    for (int mt = 0; mt < N_; mt += 64) {
        __syncthreads();
#pragma unroll
        for (int r = 0; r < 2; r++) {
            int lin = tid + r * 256;
            int d   = lin >> 4;
            int m4  = (lin & 15) * 4;
            size_t g = (size_t)(d * H_ + head) * N_ + mt + m4;
            *(float4*)&sK[d][m4] = *(const float4*)(k + g);
            float4 vv = *(const float4*)(v + g);
            sVT[m4 + 0][d] = vv.x;
            sVT[m4 + 1][d] = vv.y;
            sVT[m4 + 2][d] = vv.z;
            sVT[m4 + 3][d] = vv.w;
        }
        __syncthreads();

        float acc[4][4];
#pragma unroll
        for (int i = 0; i < 4; i++)
#pragma unroll
            for (int j = 0; j < 4; j++) acc[i][j] = 0.f;
#pragma unroll
        for (int d = 0; d < 32; d++) {
            float4 a4 = *(const float4*)&sQ[d][ty * 4];
            float4 b4 = *(const float4*)&sK[d][tx * 4];
            float a[4] = {a4.x, a4.y, a4.z, a4.w};
            float b[4] = {b4.x, b4.y, b4.z, b4.w};
#pragma unroll
            for (int i = 0; i < 4; i++)
#pragma unroll
                for (int j = 0; j < 4; j++) acc[i][j] += a[i] * b[j];
        }

        float p[4][4];
#pragma unroll
        for (int i = 0; i < 4; i++) {
            float tm = fmaxf(fmaxf(acc[i][0], acc[i][1]), fmaxf(acc[i][2], acc[i][3]));
#pragma unroll
            for (int off = 8; off > 0; off >>= 1)
                tm = fmaxf(tm, __shfl_xor_sync(0xffffffffu, tm, off));
            float newM = fmaxf(M[i], tm);
            float corr = __expf(M[i] - newM);
            M[i] = newM;
            float ls = 0.f;
#pragma unroll
            for (int j = 0; j < 4; j++) {
                p[i][j] = __expf(acc[i][j] - newM);
                ls += p[i][j];
            }
#pragma unroll
            for (int off = 8; off > 0; off >>= 1)
                ls += __shfl_xor_sync(0xffffffffu, ls, off);
            Lsum[i] = Lsum[i] * corr + ls;
            if (tx == 0) sRow[ty * 4 + i] = corr;
        }

#pragma unroll
        for (int j = 0; j < 4; j++) {
            float4 pv = make_float4(p[0][j], p[1][j], p[2][j], p[3][j]);
            *(float4*)&sP[tx * 4 + j][ty * 4] = pv;
        }
        __syncthreads();

        {
            float4 c4 = *(const float4*)&sRow[tx * 4];
            float cc[4] = {c4.x, c4.y, c4.z, c4.w};
#pragma unroll
            for (int d = 0; d < 2; d++)
#pragma unroll
                for (int j = 0; j < 4; j++) O[d][j] *= cc[j];
#pragma unroll
            for (int m = 0; m < 64; m++) {
                float2 a2 = *(const float2*)&sVT[m][ty * 2];
                float4 b4 = *(const float4*)&sP[m][tx * 4];
                O[0][0] += a2.x * b4.x;  O[0][1] += a2.x * b4.y;
                O[0][2] += a2.x * b4.z;  O[0][3] += a2.x * b4.w;
                O[1][0] += a2.y * b4.x;  O[1][1] += a2.y * b4.y;
                O[1][2] += a2.y * b4.z;  O[1][3] += a2.y * b4.w;
            }
        }
    }

    __syncthreads();
    if (tx == 0) {
#pragma unroll
        for (int i = 0; i < 4; i++) sRow[ty * 4 + i] = Lsum[i];
    }
    __syncthreads();

    {
        float4 l4 = *(const float4*)&sRow[tx * 4];
        float rl[4] = {1.f / l4.x, 1.f / l4.y, 1.f / l4.z, 1.f / l4.w};
#pragma unroll
        for (int d = 0; d < 2; d++) {
            int ch = (ty * 2 + d) * H_ + head;
            float4 o4 = make_float4(O[d][0] * rl[0], O[d][1] * rl[1],
                                    O[d][2] * rl[2], O[d][3] * rl[3]);
            *(float4*)(msg + (size_t)ch * N_ + q0 + tx * 4) = o4;
        }
    }
}

// ---------------------------------------------------------------------------
// InstanceNorm stats (unchanged).
// ---------------------------------------------------------------------------
__global__ __launch_bounds__(256) void inorm_stats_kernel(const float* __restrict__ Hbuf,
                                                          float* __restrict__ stats)
{
    const int c  = blockIdx.x;
    const int dd = blockIdx.y;
    const float4* row = (const float4*)(Hbuf + ((size_t)dd * C2_ + c) * N_);

    float s = 0.f, ss = 0.f;
    for (int i = threadIdx.x; i < N_ / 4; i += 256) {
        float4 v = row[i];
        s  += v.x + v.y + v.z + v.w;
        ss += v.x * v.x + v.y * v.y + v.z * v.z + v.w * v.w;
    }
    __shared__ float sh_s[8], sh_ss[8];
    for (int off = 16; off > 0; off >>= 1) {
        s  += __shfl_xor_sync(0xffffffffu, s,  off);
        ss += __shfl_xor_sync(0xffffffffu, ss, off);
    }
    int warp = threadIdx.x >> 5, lane = threadIdx.x & 31;
    if (lane == 0) { sh_s[warp] = s; sh_ss[warp] = ss; }
    __syncthreads();
    if (threadIdx.x == 0) {
        float ts = 0.f, tss = 0.f;
        for (int w = 0; w < 8; w++) { ts += sh_s[w]; tss += sh_ss[w]; }
        float mean = ts * (1.f / N_);
        float var  = tss * (1.f / N_) - mean * mean;
        var = fmaxf(var, 0.f);
        stats[((size_t)dd * C2_ + c) * 2 + 0] = mean;
        stats[((size_t)dd * C2_ + c) * 2 + 1] = rsqrtf(var + 1e-5f);
    }
}

__global__ __launch_bounds__(256) void init_kernel(const float* __restrict__ a,
                                                   const float* __restrict__ b,
                                                   float* __restrict__ out)
{
    int i = blockIdx.x * blockDim.x + threadIdx.x;
    const int n4 = D_ * N_ / 4;
    float4* o = (float4*)out;
    if (i < n4)           o[i] = ((const float4*)a)[i];
    else if (i < 2 * n4)  o[i] = ((const float4*)b)[i - n4];
}

// ---------------------------------------------------------------------------
// Host launcher
// ---------------------------------------------------------------------------
extern "C" void kernel_launch(void* const* d_in, const int* in_sizes, int n_in,
                              void* d_out, int out_size)
{
    const float* desc0 = (const float*)d_in[0];
    const float* desc1 = (const float*)d_in[1];
    const float* Wq = (const float*)d_in[2];
    const float* bq = (const float*)d_in[3];
    const float* Wk = (const float*)d_in[4];
    const float* bk = (const float*)d_in[5];
    const float* Wv = (const float*)d_in[6];
    const float* bv = (const float*)d_in[7];
    const float* Wm = (const float*)d_in[8];
    const float* bm = (const float*)d_in[9];
    const float* W1 = (const float*)d_in[10];
    const float* b1 = (const float*)d_in[11];
    const float* W2 = (const float*)d_in[12];
    const float* b2 = (const float*)d_in[13];

    float* x  = (float*)d_out;
    float* x0 = x;
    float* x1 = x + (size_t)D_ * N_;

    float *p_q, *p_k, *p_v, *p_msg, *p_msg2, *p_h, *p_stats;
    cudaGetSymbolAddress((void**)&p_q,     g_q);
    cudaGetSymbolAddress((void**)&p_k,     g_k);
    cudaGetSymbolAddress((void**)&p_v,     g_v);
    cudaGetSymbolAddress((void**)&p_msg,   g_msg);
    cudaGetSymbolAddress((void**)&p_msg2,  g_msg2);
    cudaGetSymbolAddress((void**)&p_h,     g_h);
    cudaGetSymbolAddress((void**)&p_stats, g_stats);

    const int BIG = 1 << 30;

    init_kernel<<<512, 256>>>(desc0, desc1, x);

    for (int l = 0; l < L_; l++) {
        const bool cross = (l & 1);
        const float* s0 = cross ? x1 : x0;
        const float* s1 = cross ? x0 : x1;

        const float* Wq_l = Wq + (size_t)l * D_ * D_;
        const float* bq_l = bq + (size_t)l * D_;
        const float* Wk_l = Wk + (size_t)l * D_ * D_;
        const float* bk_l = bk + (size_t)l * D_;
        const float* Wv_l = Wv + (size_t)l * D_ * D_;
        const float* bv_l = bv + (size_t)l * D_;
        const float* Wm_l = Wm + (size_t)l * D_ * D_;
        const float* bm_l = bm + (size_t)l * D_;
        const float* W1_l = W1 + (size_t)l * C2_ * C2_;
        const float* b1_l = b1 + (size_t)l * C2_;
        const float* W2_l = W2 + (size_t)l * D_ * C2_;
        const float* b2_l = b2 + (size_t)l * D_;

        // ---- Q/K/V projections ----
        GemmBatch bqkv{};
        bqkv.j[0] = {Wq_l, bq_l, x0, nullptr, nullptr, p_q,             D_, BIG, 0};
        bqkv.j[1] = {Wq_l, bq_l, x1, nullptr, nullptr, p_q + D_ * N_,   D_, BIG, 0};
        bqkv.j[2] = {Wk_l, bk_l, s0, nullptr, nullptr, p_k,             D_, BIG, 0};
        bqkv.j[3] = {Wk_l, bk_l, s1, nullptr, nullptr, p_k + D_ * N_,   D_, BIG, 0};
        bqkv.j[4] = {Wv_l, bv_l, s0, nullptr, nullptr, p_v,             D_, BIG, 0};
        bqkv.j[5] = {Wv_l, bv_l, s1, nullptr, nullptr, p_v + D_ * N_,   D_, BIG, 0};
        gemm_mma_kernel<<<dim3(N_ / 128, 1, 6), 256>>>(bqkv);

        // ---- attention ----
        attn_kernel<<<dim3(N_ / 64, H_, 2), 256>>>(p_q, p_k, p_v, p_msg);

        // ---- message projection ----
        GemmBatch bmsg{};
        bmsg.j[0] = {Wm_l, bm_l, p_msg,           nullptr, nullptr, p_msg2,           D_, BIG, 0};
        bmsg.j[1] = {Wm_l, bm_l, p_msg + D_ * N_, nullptr, nullptr, p_msg2 + D_ * N_, D_, BIG, 0};
        gemm_mma_kernel<<<dim3(N_ / 128, 1, 2), 256>>>(bmsg);

        // ---- MLP layer 1 (fused concat) ----
        GemmBatch bmlp1{};
        bmlp1.j[0] = {W1_l, b1_l, x0, p_msg2,           nullptr, p_h,            C2_, D_, 0};
        bmlp1.j[1] = {W1_l, b1_l, x1, p_msg2 + D_ * N_, nullptr, p_h + C2_ * N_, C2_, D_, 0};
        gemm_mma_kernel<<<dim3(N_ / 128, 2, 2), 256>>>(bmlp1);

        // ---- InstanceNorm stats ----
        inorm_stats_kernel<<<dim3(C2_, 2), 256>>>(p_h, p_stats);

        // ---- MLP layer 2 (norm+relu on load) + residual ----
        GemmBatch bmlp2{};
        bmlp2.j[0] = {W2_l, b2_l, p_h,            nullptr, p_stats,           x0, C2_, BIG, 1};
        bmlp2.j[1] = {W2_l, b2_l, p_h + C2_ * N_, nullptr, p_stats + C2_ * 2, x1, C2_, BIG, 1};
        gemm_mma_kernel<<<dim3(N_ / 128, 1, 2), 256>>>(bmlp2);
    }
}

// round 11
// speedup vs baseline: 4.0712x; 1.9720x over previous
#include <cuda_runtime.h>
#include <cstdint>
#include <math.h>

// ---------------------------------------------------------------------------
// SuperGlue-style GNN: L=6 layers, D=128, H=4, DH=32, N=2048, B=1.
// GEMMs + attention both on mma.sync tf32 tensor cores (sm_103-portable).
// ---------------------------------------------------------------------------

#define D_   128
#define N_   2048
#define L_   6
#define H_   4
#define C2_  256

__device__ float g_q   [2 * D_  * N_];
__device__ float g_k   [2 * D_  * N_];
__device__ float g_v   [2 * D_  * N_];
__device__ float g_msg [2 * D_  * N_];
__device__ float g_msg2[2 * D_  * N_];
__device__ float g_h   [2 * C2_ * N_];
__device__ float g_stats[2 * C2_ * 2];

__device__ __forceinline__ uint32_t f2tf32(float x) {
    uint32_t r;
    asm("cvt.rna.tf32.f32 %0, %1;" : "=r"(r) : "f"(x));
    return r;
}

__device__ __forceinline__ void mma_tf32(float* d, const uint32_t* a, const uint32_t* b) {
    asm volatile(
        "mma.sync.aligned.m16n8k8.row.col.f32.tf32.tf32.f32 "
        "{%0,%1,%2,%3}, {%4,%5,%6,%7}, {%8,%9}, {%0,%1,%2,%3};"
        : "+f"(d[0]), "+f"(d[1]), "+f"(d[2]), "+f"(d[3])
        : "r"(a[0]), "r"(a[1]), "r"(a[2]), "r"(a[3]), "r"(b[0]), "r"(b[1]));
}

// ---------------------------------------------------------------------------
// Batched GEMM (tensor cores):  Y[o][n] (+)= sum_k W[o][k] X[k][n] + bias[o]
// CTA 64(out) x 128(n), 8 warps (2 M x 4 N), warp tile 32x32.
// ---------------------------------------------------------------------------
struct GemmJob {
    const float* W;
    const float* bias;
    const float* X0;
    const float* X1;
    const float* stats;
    float*       Y;
    int IN;
    int split;
    int flags;
};
struct GemmBatch { GemmJob j[6]; };

#define SA_STRIDE 36
#define SB_STRIDE 136

__global__ __launch_bounds__(256) void gemm_mma_kernel(GemmBatch batch)
{
    GemmJob jb = batch.j[blockIdx.z];
    const int IN = jb.IN;
    const int KT = IN >> 5;
    const int nb = blockIdx.x * 128;
    const int ob = blockIdx.y * 64;

    __shared__ uint32_t sA[64 * SA_STRIDE];    // [m][k] tf32 bits
    __shared__ uint32_t sB[32 * SB_STRIDE];    // [k][n] tf32 bits

    const int tid  = threadIdx.x;
    const int wid  = tid >> 5;
    const int lane = tid & 31;
    const int g    = lane >> 2;
    const int c    = lane & 3;
    const int wm   = wid & 1;        // M half (32)
    const int wn   = wid >> 1;       // N quarter (32)

    float d[2][4][4];
#pragma unroll
    for (int mi = 0; mi < 2; mi++)
#pragma unroll
        for (int ni = 0; ni < 4; ni++)
#pragma unroll
            for (int r = 0; r < 4; r++) d[mi][ni][r] = 0.f;

    for (int kt = 0; kt < KT; kt++) {
        const int k0 = kt * 32;

        // ---- load A tile: W[ob..+63][k0..+31] -> sA[m][k] ----
#pragma unroll
        for (int p = 0; p < 2; p++) {
            int lin = tid + p * 256;
            int o   = lin >> 3;
            int kq  = lin & 7;
            float4 w = *(const float4*)(jb.W + (size_t)(ob + o) * IN + k0 + kq * 4);
            uint4 t = make_uint4(f2tf32(w.x), f2tf32(w.y), f2tf32(w.z), f2tf32(w.w));
            *(uint4*)&sA[o * SA_STRIDE + kq * 4] = t;
        }
        // ---- load B tile: X[k0..+31][nb..+127] -> sB[k][n] (fused ops) ----
#pragma unroll
        for (int p = 0; p < 4; p++) {
            int lin = tid + p * 256;
            int kk  = lin >> 5;
            int ng  = lin & 31;
            int r   = k0 + kk;
            const float* src = (r < jb.split) ? (jb.X0 + (size_t)r * N_)
                                              : (jb.X1 + (size_t)(r - jb.split) * N_);
            float4 xv = *(const float4*)(src + nb + ng * 4);
            if (jb.stats) {
                float mean = jb.stats[2 * r];
                float rstd = jb.stats[2 * r + 1];
                xv.x = fmaxf(0.f, (xv.x - mean) * rstd);
                xv.y = fmaxf(0.f, (xv.y - mean) * rstd);
                xv.z = fmaxf(0.f, (xv.z - mean) * rstd);
                xv.w = fmaxf(0.f, (xv.w - mean) * rstd);
            }
            uint4 t = make_uint4(f2tf32(xv.x), f2tf32(xv.y), f2tf32(xv.z), f2tf32(xv.w));
            *(uint4*)&sB[kk * SB_STRIDE + ng * 4] = t;
        }
        __syncthreads();

#pragma unroll
        for (int ks = 0; ks < 4; ks++) {
            int kc = ks * 8 + c;
            uint32_t a[2][4];
#pragma unroll
            for (int mi = 0; mi < 2; mi++) {
                int row = wm * 32 + mi * 16;
                a[mi][0] = sA[(row + g)     * SA_STRIDE + kc];
                a[mi][1] = sA[(row + g + 8) * SA_STRIDE + kc];
                a[mi][2] = sA[(row + g)     * SA_STRIDE + kc + 4];
                a[mi][3] = sA[(row + g + 8) * SA_STRIDE + kc + 4];
            }
#pragma unroll
            for (int ni = 0; ni < 4; ni++) {
                int col = wn * 32 + ni * 8 + g;
                uint32_t b[2];
                b[0] = sB[(ks * 8 + c)     * SB_STRIDE + col];
                b[1] = sB[(ks * 8 + c + 4) * SB_STRIDE + col];
#pragma unroll
                for (int mi = 0; mi < 2; mi++)
                    mma_tf32(d[mi][ni], a[mi], b);
            }
        }
        __syncthreads();
    }

    // ---- epilogue: bias + optional residual ----
#pragma unroll
    for (int mi = 0; mi < 2; mi++) {
        int orow = ob + wm * 32 + mi * 16 + g;
        float bias0 = jb.bias ? jb.bias[orow]     : 0.f;
        float bias1 = jb.bias ? jb.bias[orow + 8] : 0.f;
        float* y0 = jb.Y + (size_t)orow * N_;
        float* y1 = jb.Y + (size_t)(orow + 8) * N_;
#pragma unroll
        for (int ni = 0; ni < 4; ni++) {
            int ncol = nb + wn * 32 + ni * 8 + c * 2;
            float2 v0 = make_float2(d[mi][ni][0] + bias0, d[mi][ni][1] + bias0);
            float2 v1 = make_float2(d[mi][ni][2] + bias1, d[mi][ni][3] + bias1);
            if (jb.flags & 1) {
                float2 o0 = *(const float2*)(y0 + ncol);
                float2 o1 = *(const float2*)(y1 + ncol);
                v0.x += o0.x; v0.y += o0.y;
                v1.x += o1.x; v1.y += o1.y;
            }
            *(float2*)(y0 + ncol) = v0;
            *(float2*)(y1 + ncol) = v1;
        }
    }
}

// ---------------------------------------------------------------------------
// Flash attention on mma.sync tf32.
// Block: 128 queries x one (head, desc); 8 warps, 16 q each. Key tiles of 64.
// S-phase: S[16q x 64k] = Q^T x K  (A = sQT[q][d], B = sK[d][key]).
// O-phase: O^T[32d x 16q] = V x P  (A = sV[d][key], B = sP[key][q]).
// sP holds ALL 128 query columns (stride 136 — this was the R9 bug: stride 68
// overflowed for warps with qw >= 64, corrupting other warps' P rows).
// Grid (N/128, H, 2).
// ---------------------------------------------------------------------------
#define SQ  68
#define SKS 72
#define SVS 68
#define SPS 136
#define ATT_SMEM_WORDS (128 * SQ + 32 * SKS + 32 * SVS + 64 * SPS + 256)
#define ATT_SMEM_BYTES (ATT_SMEM_WORDS * 4)

__global__ __launch_bounds__(256) void attn_mma_kernel(const float* __restrict__ gq,
                                                       const float* __restrict__ gk,
                                                       const float* __restrict__ gv,
                                                       float* __restrict__ gmsg)
{
    extern __shared__ uint32_t sm[];
    uint32_t* sQT = sm;                      // [128][SQ]  Q^T tf32 (prescaled)
    uint32_t* sK  = sQT + 128 * SQ;          // [32][SKS]  K tf32 [d][key]
    uint32_t* sV  = sK  + 32 * SKS;          // [32][SVS]  V tf32 [d][key]
    uint32_t* sP  = sV  + 32 * SVS;          // [64][SPS]  P tf32 [key][q], q=0..127
    float* sCorr  = (float*)(sP + 64 * SPS); // [128]
    float* sL     = sCorr + 128;             // [128]

    const int head = blockIdx.y;
    const int desc = blockIdx.z;
    const size_t base = (size_t)desc * D_ * N_;
    const float* q = gq + base;
    const float* k = gk + base;
    const float* v = gv + base;
    float* msg = gmsg + base;

    const int tid  = threadIdx.x;
    const int wid  = tid >> 5;
    const int lane = tid & 31;
    const int g    = lane >> 2;
    const int c    = lane & 3;
    const int q0   = blockIdx.x * 128;
    const int qw   = wid * 16;               // warp's query base (local)

    // ---- load Q^T (128 q x 32 d), prescaled tf32 ----
    {
        const float scale = 0.17677669529663687f;   // 1/sqrt(32)
#pragma unroll
        for (int it = 0; it < 4; it++) {
            int lin = tid + it * 256;
            int d   = lin >> 5;
            int q4  = (lin & 31) * 4;
            float4 x = *(const float4*)(q + (size_t)(d * H_ + head) * N_ + q0 + q4);
            sQT[(q4 + 0) * SQ + d] = f2tf32(x.x * scale);
            sQT[(q4 + 1) * SQ + d] = f2tf32(x.y * scale);
            sQT[(q4 + 2) * SQ + d] = f2tf32(x.z * scale);
            sQT[(q4 + 3) * SQ + d] = f2tf32(x.w * scale);
        }
    }

    float M[2] = {-1e30f, -1e30f};
    float L[2] = {0.f, 0.f};
    float o[2][2][4];
#pragma unroll
    for (int mi = 0; mi < 2; mi++)
#pragma unroll
        for (int nq = 0; nq < 2; nq++)
#pragma unroll
            for (int r = 0; r < 4; r++) o[mi][nq][r] = 0.f;

    for (int mt = 0; mt < N_; mt += 64) {
        __syncthreads();
        // ---- load K, V tiles (32 d x 64 keys each) ----
#pragma unroll
        for (int it = 0; it < 2; it++) {
            int lin = tid + it * 256;
            int d   = lin >> 4;
            int k4  = (lin & 15) * 4;
            size_t gidx = (size_t)(d * H_ + head) * N_ + mt + k4;
            float4 kk = *(const float4*)(k + gidx);
            *(uint4*)&sK[d * SKS + k4] =
                make_uint4(f2tf32(kk.x), f2tf32(kk.y), f2tf32(kk.z), f2tf32(kk.w));
            float4 vv = *(const float4*)(v + gidx);
            *(uint4*)&sV[d * SVS + k4] =
                make_uint4(f2tf32(vv.x), f2tf32(vv.y), f2tf32(vv.z), f2tf32(vv.w));
        }
        __syncthreads();

        // ---- S-phase: S[16q x 64k] ----
        float s[8][4];
#pragma unroll
        for (int ni = 0; ni < 8; ni++)
#pragma unroll
            for (int r = 0; r < 4; r++) s[ni][r] = 0.f;
#pragma unroll
        for (int ks = 0; ks < 4; ks++) {
            int kc = ks * 8 + c;
            uint32_t a[4];
            a[0] = sQT[(qw + g)     * SQ + kc];
            a[1] = sQT[(qw + g + 8) * SQ + kc];
            a[2] = sQT[(qw + g)     * SQ + kc + 4];
            a[3] = sQT[(qw + g + 8) * SQ + kc + 4];
#pragma unroll
            for (int ni = 0; ni < 8; ni++) {
                uint32_t b[2];
                b[0] = sK[(ks * 8 + c)     * SKS + ni * 8 + g];
                b[1] = sK[(ks * 8 + c + 4) * SKS + ni * 8 + g];
                mma_tf32(s[ni], a, b);
            }
        }

        // ---- online softmax (rows g and g+8) ----
#pragma unroll
        for (int r = 0; r < 2; r++) {
            const int i0 = r * 2;
            float tm = -1e30f;
#pragma unroll
            for (int ni = 0; ni < 8; ni++)
                tm = fmaxf(tm, fmaxf(s[ni][i0], s[ni][i0 + 1]));
            tm = fmaxf(tm, __shfl_xor_sync(0xffffffffu, tm, 1));
            tm = fmaxf(tm, __shfl_xor_sync(0xffffffffu, tm, 2));
            float newM = fmaxf(M[r], tm);
            float corr = __expf(M[r] - newM);
            M[r] = newM;
            float ls = 0.f;
#pragma unroll
            for (int ni = 0; ni < 8; ni++) {
                s[ni][i0]     = __expf(s[ni][i0]     - newM);
                s[ni][i0 + 1] = __expf(s[ni][i0 + 1] - newM);
                ls += s[ni][i0] + s[ni][i0 + 1];
            }
            ls += __shfl_xor_sync(0xffffffffu, ls, 1);
            ls += __shfl_xor_sync(0xffffffffu, ls, 2);
            L[r] = L[r] * corr + ls;
            if (c == 0) sCorr[qw + g + r * 8] = corr;
        }

        // ---- write P -> sP [key][q] (tf32) ----
#pragma unroll
        for (int ni = 0; ni < 8; ni++) {
            int key = ni * 8 + c * 2;
            sP[(key    ) * SPS + qw + g]     = f2tf32(s[ni][0]);
            sP[(key + 1) * SPS + qw + g]     = f2tf32(s[ni][1]);
            sP[(key    ) * SPS + qw + g + 8] = f2tf32(s[ni][2]);
            sP[(key + 1) * SPS + qw + g + 8] = f2tf32(s[ni][3]);
        }
        __syncthreads();

        // ---- O-phase: O^T[32d x 16q] += V x P ----
        float cc[2][2];
#pragma unroll
        for (int nq = 0; nq < 2; nq++) {
            cc[nq][0] = sCorr[qw + nq * 8 + c * 2];
            cc[nq][1] = sCorr[qw + nq * 8 + c * 2 + 1];
        }
#pragma unroll
        for (int mi = 0; mi < 2; mi++)
#pragma unroll
            for (int nq = 0; nq < 2; nq++) {
                o[mi][nq][0] *= cc[nq][0];
                o[mi][nq][1] *= cc[nq][1];
                o[mi][nq][2] *= cc[nq][0];
                o[mi][nq][3] *= cc[nq][1];
            }
#pragma unroll
        for (int ks = 0; ks < 8; ks++) {
            int kc = ks * 8 + c;
            uint32_t a[2][4];
#pragma unroll
            for (int mi = 0; mi < 2; mi++) {
                a[mi][0] = sV[(mi * 16 + g)     * SVS + kc];
                a[mi][1] = sV[(mi * 16 + g + 8) * SVS + kc];
                a[mi][2] = sV[(mi * 16 + g)     * SVS + kc + 4];
                a[mi][3] = sV[(mi * 16 + g + 8) * SVS + kc + 4];
            }
#pragma unroll
            for (int nq = 0; nq < 2; nq++) {
                uint32_t b[2];
                b[0] = sP[(ks * 8 + c)     * SPS + qw + nq * 8 + g];
                b[1] = sP[(ks * 8 + c + 4) * SPS + qw + nq * 8 + g];
                mma_tf32(o[0][nq], a[0], b);
                mma_tf32(o[1][nq], a[1], b);
            }
        }
    }

    // ---- finalize: divide by L, store O^T rows (= channels) ----
    if (c == 0) {
        sL[qw + g]     = L[0];
        sL[qw + g + 8] = L[1];
    }
    __syncthreads();

    float rl[2][2];
#pragma unroll
    for (int nq = 0; nq < 2; nq++) {
        rl[nq][0] = 1.f / sL[qw + nq * 8 + c * 2];
        rl[nq][1] = 1.f / sL[qw + nq * 8 + c * 2 + 1];
    }
#pragma unroll
    for (int mi = 0; mi < 2; mi++) {
        int d0 = mi * 16 + g;
#pragma unroll
        for (int nq = 0; nq < 2; nq++) {
            int qc = q0 + qw + nq * 8 + c * 2;
            float2 v0 = make_float2(o[mi][nq][0] * rl[nq][0], o[mi][nq][1] * rl[nq][1]);
            float2 v1 = make_float2(o[mi][nq][2] * rl[nq][0], o[mi][nq][3] * rl[nq][1]);
            *(float2*)(msg + (size_t)(d0 * H_ + head) * N_ + qc)       = v0;
            *(float2*)(msg + (size_t)((d0 + 8) * H_ + head) * N_ + qc) = v1;
        }
    }
}

// ---------------------------------------------------------------------------
// InstanceNorm stats (unchanged).
// ---------------------------------------------------------------------------
__global__ __launch_bounds__(256) void inorm_stats_kernel(const float* __restrict__ Hbuf,
                                                          float* __restrict__ stats)
{
    const int c  = blockIdx.x;
    const int dd = blockIdx.y;
    const float4* row = (const float4*)(Hbuf + ((size_t)dd * C2_ + c) * N_);

    float s = 0.f, ss = 0.f;
    for (int i = threadIdx.x; i < N_ / 4; i += 256) {
        float4 v = row[i];
        s  += v.x + v.y + v.z + v.w;
        ss += v.x * v.x + v.y * v.y + v.z * v.z + v.w * v.w;
    }
    __shared__ float sh_s[8], sh_ss[8];
    for (int off = 16; off > 0; off >>= 1) {
        s  += __shfl_xor_sync(0xffffffffu, s,  off);
        ss += __shfl_xor_sync(0xffffffffu, ss, off);
    }
    int warp = threadIdx.x >> 5, lane = threadIdx.x & 31;
    if (lane == 0) { sh_s[warp] = s; sh_ss[warp] = ss; }
    __syncthreads();
    if (threadIdx.x == 0) {
        float ts = 0.f, tss = 0.f;
        for (int w = 0; w < 8; w++) { ts += sh_s[w]; tss += sh_ss[w]; }
        float mean = ts * (1.f / N_);
        float var  = tss * (1.f / N_) - mean * mean;
        var = fmaxf(var, 0.f);
        stats[((size_t)dd * C2_ + c) * 2 + 0] = mean;
        stats[((size_t)dd * C2_ + c) * 2 + 1] = rsqrtf(var + 1e-5f);
    }
}

__global__ __launch_bounds__(256) void init_kernel(const float* __restrict__ a,
                                                   const float* __restrict__ b,
                                                   float* __restrict__ out)
{
    int i = blockIdx.x * blockDim.x + threadIdx.x;
    const int n4 = D_ * N_ / 4;
    float4* o = (float4*)out;
    if (i < n4)           o[i] = ((const float4*)a)[i];
    else if (i < 2 * n4)  o[i] = ((const float4*)b)[i - n4];
}

// ---------------------------------------------------------------------------
// Host launcher
// ---------------------------------------------------------------------------
extern "C" void kernel_launch(void* const* d_in, const int* in_sizes, int n_in,
                              void* d_out, int out_size)
{
    const float* desc0 = (const float*)d_in[0];
    const float* desc1 = (const float*)d_in[1];
    const float* Wq = (const float*)d_in[2];
    const float* bq = (const float*)d_in[3];
    const float* Wk = (const float*)d_in[4];
    const float* bk = (const float*)d_in[5];
    const float* Wv = (const float*)d_in[6];
    const float* bv = (const float*)d_in[7];
    const float* Wm = (const float*)d_in[8];
    const float* bm = (const float*)d_in[9];
    const float* W1 = (const float*)d_in[10];
    const float* b1 = (const float*)d_in[11];
    const float* W2 = (const float*)d_in[12];
    const float* b2 = (const float*)d_in[13];

    float* x  = (float*)d_out;
    float* x0 = x;
    float* x1 = x + (size_t)D_ * N_;

    float *p_q, *p_k, *p_v, *p_msg, *p_msg2, *p_h, *p_stats;
    cudaGetSymbolAddress((void**)&p_q,     g_q);
    cudaGetSymbolAddress((void**)&p_k,     g_k);
    cudaGetSymbolAddress((void**)&p_v,     g_v);
    cudaGetSymbolAddress((void**)&p_msg,   g_msg);
    cudaGetSymbolAddress((void**)&p_msg2,  g_msg2);
    cudaGetSymbolAddress((void**)&p_h,     g_h);
    cudaGetSymbolAddress((void**)&p_stats, g_stats);

    cudaFuncSetAttribute(attn_mma_kernel,
                         cudaFuncAttributeMaxDynamicSharedMemorySize, ATT_SMEM_BYTES);

    const int BIG = 1 << 30;

    init_kernel<<<512, 256>>>(desc0, desc1, x);

    for (int l = 0; l < L_; l++) {
        const bool cross = (l & 1);
        const float* s0 = cross ? x1 : x0;
        const float* s1 = cross ? x0 : x1;

        const float* Wq_l = Wq + (size_t)l * D_ * D_;
        const float* bq_l = bq + (size_t)l * D_;
        const float* Wk_l = Wk + (size_t)l * D_ * D_;
        const float* bk_l = bk + (size_t)l * D_;
        const float* Wv_l = Wv + (size_t)l * D_ * D_;
        const float* bv_l = bv + (size_t)l * D_;
        const float* Wm_l = Wm + (size_t)l * D_ * D_;
        const float* bm_l = bm + (size_t)l * D_;
        const float* W1_l = W1 + (size_t)l * C2_ * C2_;
        const float* b1_l = b1 + (size_t)l * C2_;
        const float* W2_l = W2 + (size_t)l * D_ * C2_;
        const float* b2_l = b2 + (size_t)l * D_;

        // ---- Q/K/V projections ----
        GemmBatch bqkv{};
        bqkv.j[0] = {Wq_l, bq_l, x0, nullptr, nullptr, p_q,             D_, BIG, 0};
        bqkv.j[1] = {Wq_l, bq_l, x1, nullptr, nullptr, p_q + D_ * N_,   D_, BIG, 0};
        bqkv.j[2] = {Wk_l, bk_l, s0, nullptr, nullptr, p_k,             D_, BIG, 0};
        bqkv.j[3] = {Wk_l, bk_l, s1, nullptr, nullptr, p_k + D_ * N_,   D_, BIG, 0};
        bqkv.j[4] = {Wv_l, bv_l, s0, nullptr, nullptr, p_v,             D_, BIG, 0};
        bqkv.j[5] = {Wv_l, bv_l, s1, nullptr, nullptr, p_v + D_ * N_,   D_, BIG, 0};
        gemm_mma_kernel<<<dim3(N_ / 128, D_ / 64, 6), 256>>>(bqkv);

        // ---- attention (tensor cores) ----
        attn_mma_kernel<<<dim3(N_ / 128, H_, 2), 256, ATT_SMEM_BYTES>>>(p_q, p_k, p_v, p_msg);

        // ---- message projection ----
        GemmBatch bmsg{};
        bmsg.j[0] = {Wm_l, bm_l, p_msg,           nullptr, nullptr, p_msg2,           D_, BIG, 0};
        bmsg.j[1] = {Wm_l, bm_l, p_msg + D_ * N_, nullptr, nullptr, p_msg2 + D_ * N_, D_, BIG, 0};
        gemm_mma_kernel<<<dim3(N_ / 128, D_ / 64, 2), 256>>>(bmsg);

        // ---- MLP layer 1 (fused concat) ----
        GemmBatch bmlp1{};
        bmlp1.j[0] = {W1_l, b1_l, x0, p_msg2,           nullptr, p_h,            C2_, D_, 0};
        bmlp1.j[1] = {W1_l, b1_l, x1, p_msg2 + D_ * N_, nullptr, p_h + C2_ * N_, C2_, D_, 0};
        gemm_mma_kernel<<<dim3(N_ / 128, C2_ / 64, 2), 256>>>(bmlp1);

        // ---- InstanceNorm stats ----
        inorm_stats_kernel<<<dim3(C2_, 2), 256>>>(p_h, p_stats);

        // ---- MLP layer 2 (norm+relu on load) + residual ----
        GemmBatch bmlp2{};
        bmlp2.j[0] = {W2_l, b2_l, p_h,            nullptr, p_stats,           x0, C2_, BIG, 1};
        bmlp2.j[1] = {W2_l, b2_l, p_h + C2_ * N_, nullptr, p_stats + C2_ * 2, x1, C2_, BIG, 1};
        gemm_mma_kernel<<<dim3(N_ / 128, D_ / 64, 2), 256>>>(bmlp2);
    }
}

// round 12
// speedup vs baseline: 5.2732x; 1.2953x over previous
#include <cuda_runtime.h>
#include <cstdint>
#include <math.h>

// ---------------------------------------------------------------------------
// SuperGlue-style GNN: L=6 layers, D=128, H=4, DH=32, N=2048, B=1.
// GEMMs + attention on mma.sync tf32. Wm fused into W1 (precomputed).
// ---------------------------------------------------------------------------

#define D_   128
#define N_   2048
#define L_   6
#define H_   4
#define C2_  256

__device__ float g_q   [2 * D_  * N_];
__device__ float g_k   [2 * D_  * N_];
__device__ float g_v   [2 * D_  * N_];
__device__ float g_msg [2 * D_  * N_];
__device__ float g_h   [2 * C2_ * N_];
__device__ float g_stats[2 * C2_ * 2];
__device__ float g_wf  [L_ * C2_ * C2_];   // fused MLP1 weights
__device__ float g_bf  [L_ * C2_];         // fused MLP1 bias

__device__ __forceinline__ uint32_t f2tf32(float x) {
    uint32_t r;
    asm("cvt.rna.tf32.f32 %0, %1;" : "=r"(r) : "f"(x));
    return r;
}

__device__ __forceinline__ void mma_tf32(float* d, const uint32_t* a, const uint32_t* b) {
    asm volatile(
        "mma.sync.aligned.m16n8k8.row.col.f32.tf32.tf32.f32 "
        "{%0,%1,%2,%3}, {%4,%5,%6,%7}, {%8,%9}, {%0,%1,%2,%3};"
        : "+f"(d[0]), "+f"(d[1]), "+f"(d[2]), "+f"(d[3])
        : "r"(a[0]), "r"(a[1]), "r"(a[2]), "r"(a[3]), "r"(b[0]), "r"(b[1]));
}

// ---------------------------------------------------------------------------
// Precompute fused MLP1:  wf[:, :128] = W1[:, :128]
//                         wf[:, 128:] = W1[:, 128:] @ Wm
//                         bf          = W1[:, 128:] @ bm + b1
// grid 6*256 blocks, 128 threads.
// ---------------------------------------------------------------------------
__global__ __launch_bounds__(128) void fuse_w1_kernel(const float* __restrict__ W1,
                                                      const float* __restrict__ b1,
                                                      const float* __restrict__ Wm,
                                                      const float* __restrict__ bm,
                                                      float* __restrict__ wf,
                                                      float* __restrict__ bf)
{
    const int l = blockIdx.x >> 8;
    const int o = blockIdx.x & 255;
    const int t = threadIdx.x;

    __shared__ float sw[256];
    __shared__ float red[4];

    const float* w1row = W1 + ((size_t)l * C2_ + o) * C2_;
    sw[t]       = w1row[t];
    sw[t + 128] = w1row[t + 128];
    __syncthreads();

    float* out = wf + ((size_t)l * C2_ + o) * C2_;
    out[t] = sw[t];   // left half copy

    const float* wm = Wm + (size_t)l * D_ * D_;
    float acc = 0.f;
#pragma unroll 8
    for (int j = 0; j < 128; j++)
        acc += sw[128 + j] * wm[j * 128 + t];
    out[128 + t] = acc;

    // bias: sum_j W1b[o][j] * bm[j]
    float tb = sw[128 + t] * bm[l * D_ + t];
#pragma unroll
    for (int off = 16; off > 0; off >>= 1)
        tb += __shfl_xor_sync(0xffffffffu, tb, off);
    if ((t & 31) == 0) red[t >> 5] = tb;
    __syncthreads();
    if (t == 0)
        bf[l * C2_ + o] = red[0] + red[1] + red[2] + red[3] + b1[(size_t)l * C2_ + o];
}

// ---------------------------------------------------------------------------
// Batched GEMM (tensor cores), register-staged K pipeline.
// CTA 64(out) x NTILE(n), 8 warps (2 M x 4 N).
// ---------------------------------------------------------------------------
struct GemmJob {
    const float* W;
    const float* bias;
    const float* X0;
    const float* X1;
    const float* stats;
    float*       Y;
    int IN;
    int split;
    int flags;
};
struct GemmBatch { GemmJob j[6]; };

#define SA_STRIDE 36

template<int NTILE>
__global__ __launch_bounds__(256) void gemm_mma_kernel(GemmBatch batch)
{
    constexpr int F4PR = NTILE / 4;       // float4 slots per B row
    constexpr int SBS  = NTILE + 8;       // B stride (keeps 8c+g bank pattern)
    constexpr int NI   = NTILE / 32;      // warp N microtiles
    constexpr int BP   = NTILE / 32;      // B load iterations per thread

    GemmJob jb = batch.j[blockIdx.z];
    const int IN = jb.IN;
    const int KT = IN >> 5;
    const int nb = blockIdx.x * NTILE;
    const int ob = blockIdx.y * 64;

    __shared__ uint32_t sA[64 * SA_STRIDE];
    __shared__ uint32_t sB[32 * SBS];

    const int tid  = threadIdx.x;
    const int wid  = tid >> 5;
    const int lane = tid & 31;
    const int g    = lane >> 2;
    const int c    = lane & 3;
    const int wm   = wid & 1;
    const int wn   = wid >> 1;

    float4 wreg[2];
    float4 xreg[BP];
    float2 msreg[BP];

    auto ldg_tiles = [&](int k0) {
#pragma unroll
        for (int p = 0; p < 2; p++) {
            int lin = tid + p * 256;
            int o   = lin >> 3;
            int kq  = lin & 7;
            wreg[p] = *(const float4*)(jb.W + (size_t)(ob + o) * IN + k0 + kq * 4);
        }
#pragma unroll
        for (int p = 0; p < BP; p++) {
            int lin = tid + p * 256;
            int kk  = lin / F4PR;
            int ng  = lin % F4PR;
            int r   = k0 + kk;
            const float* src = (r < jb.split) ? (jb.X0 + (size_t)r * N_)
                                              : (jb.X1 + (size_t)(r - jb.split) * N_);
            xreg[p] = *(const float4*)(src + nb + ng * 4);
            if (jb.stats) msreg[p] = *(const float2*)(jb.stats + 2 * r);
        }
    };
    auto sts_tiles = [&]() {
#pragma unroll
        for (int p = 0; p < 2; p++) {
            int lin = tid + p * 256;
            int o   = lin >> 3;
            int kq  = lin & 7;
            float4 w = wreg[p];
            *(uint4*)&sA[o * SA_STRIDE + kq * 4] =
                make_uint4(f2tf32(w.x), f2tf32(w.y), f2tf32(w.z), f2tf32(w.w));
        }
#pragma unroll
        for (int p = 0; p < BP; p++) {
            int lin = tid + p * 256;
            int kk  = lin / F4PR;
            int ng  = lin % F4PR;
            float4 xv = xreg[p];
            if (jb.stats) {
                float mean = msreg[p].x, rstd = msreg[p].y;
                xv.x = fmaxf(0.f, (xv.x - mean) * rstd);
                xv.y = fmaxf(0.f, (xv.y - mean) * rstd);
                xv.z = fmaxf(0.f, (xv.z - mean) * rstd);
                xv.w = fmaxf(0.f, (xv.w - mean) * rstd);
            }
            *(uint4*)&sB[kk * SBS + ng * 4] =
                make_uint4(f2tf32(xv.x), f2tf32(xv.y), f2tf32(xv.z), f2tf32(xv.w));
        }
    };

    float d[2][NI][4];
#pragma unroll
    for (int mi = 0; mi < 2; mi++)
#pragma unroll
        for (int ni = 0; ni < NI; ni++)
#pragma unroll
            for (int r = 0; r < 4; r++) d[mi][ni][r] = 0.f;

    ldg_tiles(0);
    sts_tiles();
    __syncthreads();

    for (int kt = 0; kt < KT; kt++) {
        const bool have_next = (kt + 1 < KT);
        if (have_next) ldg_tiles((kt + 1) * 32);

#pragma unroll
        for (int ks = 0; ks < 4; ks++) {
            int kc = ks * 8 + c;
            uint32_t a[2][4];
#pragma unroll
            for (int mi = 0; mi < 2; mi++) {
                int row = wm * 32 + mi * 16;
                a[mi][0] = sA[(row + g)     * SA_STRIDE + kc];
                a[mi][1] = sA[(row + g + 8) * SA_STRIDE + kc];
                a[mi][2] = sA[(row + g)     * SA_STRIDE + kc + 4];
                a[mi][3] = sA[(row + g + 8) * SA_STRIDE + kc + 4];
            }
#pragma unroll
            for (int ni = 0; ni < NI; ni++) {
                int col = wn * (NTILE / 4) + ni * 8 + g;
                uint32_t b[2];
                b[0] = sB[(ks * 8 + c)     * SBS + col];
                b[1] = sB[(ks * 8 + c + 4) * SBS + col];
#pragma unroll
                for (int mi = 0; mi < 2; mi++)
                    mma_tf32(d[mi][ni], a[mi], b);
            }
        }
        __syncthreads();
        if (have_next) {
            sts_tiles();
            __syncthreads();
        }
    }

    // ---- epilogue ----
#pragma unroll
    for (int mi = 0; mi < 2; mi++) {
        int orow = ob + wm * 32 + mi * 16 + g;
        float bias0 = jb.bias ? jb.bias[orow]     : 0.f;
        float bias1 = jb.bias ? jb.bias[orow + 8] : 0.f;
        float* y0 = jb.Y + (size_t)orow * N_;
        float* y1 = jb.Y + (size_t)(orow + 8) * N_;
#pragma unroll
        for (int ni = 0; ni < NI; ni++) {
            int ncol = nb + wn * (NTILE / 4) + ni * 8 + c * 2;
            float2 v0 = make_float2(d[mi][ni][0] + bias0, d[mi][ni][1] + bias0);
            float2 v1 = make_float2(d[mi][ni][2] + bias1, d[mi][ni][3] + bias1);
            if (jb.flags & 1) {
                float2 o0 = *(const float2*)(y0 + ncol);
                float2 o1 = *(const float2*)(y1 + ncol);
                v0.x += o0.x; v0.y += o0.y;
                v1.x += o1.x; v1.y += o1.y;
            }
            *(float2*)(y0 + ncol) = v0;
            *(float2*)(y1 + ncol) = v1;
        }
    }
}

// ---------------------------------------------------------------------------
// Flash attention on mma.sync tf32, double-buffered K/V.
// Block: 128 queries x (head, desc); 8 warps. Key tiles of 64.
// ---------------------------------------------------------------------------
#define SQ  68
#define SKS 72
#define SVS 68
#define SPS 136
#define KV_WORDS (32 * SKS + 32 * SVS)
#define ATT_SMEM_WORDS (128 * SQ + 2 * KV_WORDS + 64 * SPS + 256)
#define ATT_SMEM_BYTES (ATT_SMEM_WORDS * 4)

__global__ __launch_bounds__(256) void attn_mma_kernel(const float* __restrict__ gq,
                                                       const float* __restrict__ gk,
                                                       const float* __restrict__ gv,
                                                       float* __restrict__ gmsg)
{
    extern __shared__ uint32_t sm[];
    uint32_t* sQT  = sm;                         // [128][SQ]
    uint32_t* sKV  = sQT + 128 * SQ;             // 2 x ([32][SKS] K + [32][SVS] V)
    uint32_t* sP   = sKV + 2 * KV_WORDS;         // [64][SPS]
    float* sCorr   = (float*)(sP + 64 * SPS);    // [128]
    float* sL      = sCorr + 128;                // [128]

    const int head = blockIdx.y;
    const int desc = blockIdx.z;
    const size_t base = (size_t)desc * D_ * N_;
    const float* q = gq + base;
    const float* k = gk + base;
    const float* v = gv + base;
    float* msg = gmsg + base;

    const int tid  = threadIdx.x;
    const int wid  = tid >> 5;
    const int lane = tid & 31;
    const int g    = lane >> 2;
    const int c    = lane & 3;
    const int q0   = blockIdx.x * 128;
    const int qw   = wid * 16;

    // ---- load Q^T prescaled ----
    {
        const float scale = 0.17677669529663687f;
#pragma unroll
        for (int it = 0; it < 4; it++) {
            int lin = tid + it * 256;
            int d   = lin >> 5;
            int q4  = (lin & 31) * 4;
            float4 x = *(const float4*)(q + (size_t)(d * H_ + head) * N_ + q0 + q4);
            sQT[(q4 + 0) * SQ + d] = f2tf32(x.x * scale);
            sQT[(q4 + 1) * SQ + d] = f2tf32(x.y * scale);
            sQT[(q4 + 2) * SQ + d] = f2tf32(x.z * scale);
            sQT[(q4 + 3) * SQ + d] = f2tf32(x.w * scale);
        }
    }

    float4 kreg[2], vreg[2];
    auto ldg_kv = [&](int mt) {
#pragma unroll
        for (int it = 0; it < 2; it++) {
            int lin = tid + it * 256;
            int d   = lin >> 4;
            int k4  = (lin & 15) * 4;
            size_t gidx = (size_t)(d * H_ + head) * N_ + mt + k4;
            kreg[it] = *(const float4*)(k + gidx);
            vreg[it] = *(const float4*)(v + gidx);
        }
    };
    auto sts_kv = [&](int buf) {
        uint32_t* sK = sKV + buf * KV_WORDS;
        uint32_t* sV = sK + 32 * SKS;
#pragma unroll
        for (int it = 0; it < 2; it++) {
            int lin = tid + it * 256;
            int d   = lin >> 4;
            int k4  = (lin & 15) * 4;
            float4 kk = kreg[it];
            *(uint4*)&sK[d * SKS + k4] =
                make_uint4(f2tf32(kk.x), f2tf32(kk.y), f2tf32(kk.z), f2tf32(kk.w));
            float4 vv = vreg[it];
            *(uint4*)&sV[d * SVS + k4] =
                make_uint4(f2tf32(vv.x), f2tf32(vv.y), f2tf32(vv.z), f2tf32(vv.w));
        }
    };

    float M[2] = {-1e30f, -1e30f};
    float L[2] = {0.f, 0.f};
    float o[2][2][4];
#pragma unroll
    for (int mi = 0; mi < 2; mi++)
#pragma unroll
        for (int nq = 0; nq < 2; nq++)
#pragma unroll
            for (int r = 0; r < 4; r++) o[mi][nq][r] = 0.f;

    ldg_kv(0);
    sts_kv(0);
    __syncthreads();
    int buf = 0;

    for (int mt = 0; mt < N_; mt += 64) {
        const bool have_next = (mt + 64 < N_);
        if (have_next) ldg_kv(mt + 64);

        uint32_t* sK = sKV + buf * KV_WORDS;
        uint32_t* sV = sK + 32 * SKS;

        // ---- S-phase ----
        float s[8][4];
#pragma unroll
        for (int ni = 0; ni < 8; ni++)
#pragma unroll
            for (int r = 0; r < 4; r++) s[ni][r] = 0.f;
#pragma unroll
        for (int ks = 0; ks < 4; ks++) {
            int kc = ks * 8 + c;
            uint32_t a[4];
            a[0] = sQT[(qw + g)     * SQ + kc];
            a[1] = sQT[(qw + g + 8) * SQ + kc];
            a[2] = sQT[(qw + g)     * SQ + kc + 4];
            a[3] = sQT[(qw + g + 8) * SQ + kc + 4];
#pragma unroll
            for (int ni = 0; ni < 8; ni++) {
                uint32_t b[2];
                b[0] = sK[(ks * 8 + c)     * SKS + ni * 8 + g];
                b[1] = sK[(ks * 8 + c + 4) * SKS + ni * 8 + g];
                mma_tf32(s[ni], a, b);
            }
        }

        if (have_next) sts_kv(buf ^ 1);   // overlapped with softmax below

        // ---- online softmax ----
#pragma unroll
        for (int r = 0; r < 2; r++) {
            const int i0 = r * 2;
            float tm = -1e30f;
#pragma unroll
            for (int ni = 0; ni < 8; ni++)
                tm = fmaxf(tm, fmaxf(s[ni][i0], s[ni][i0 + 1]));
            tm = fmaxf(tm, __shfl_xor_sync(0xffffffffu, tm, 1));
            tm = fmaxf(tm, __shfl_xor_sync(0xffffffffu, tm, 2));
            float newM = fmaxf(M[r], tm);
            float corr = __expf(M[r] - newM);
            M[r] = newM;
            float ls = 0.f;
#pragma unroll
            for (int ni = 0; ni < 8; ni++) {
                s[ni][i0]     = __expf(s[ni][i0]     - newM);
                s[ni][i0 + 1] = __expf(s[ni][i0 + 1] - newM);
                ls += s[ni][i0] + s[ni][i0 + 1];
            }
            ls += __shfl_xor_sync(0xffffffffu, ls, 1);
            ls += __shfl_xor_sync(0xffffffffu, ls, 2);
            L[r] = L[r] * corr + ls;
            if (c == 0) sCorr[qw + g + r * 8] = corr;
        }

        // ---- write P ----
#pragma unroll
        for (int ni = 0; ni < 8; ni++) {
            int key = ni * 8 + c * 2;
            sP[(key    ) * SPS + qw + g]     = f2tf32(s[ni][0]);
            sP[(key + 1) * SPS + qw + g]     = f2tf32(s[ni][1]);
            sP[(key    ) * SPS + qw + g + 8] = f2tf32(s[ni][2]);
            sP[(key + 1) * SPS + qw + g + 8] = f2tf32(s[ni][3]);
        }
        __syncthreads();

        // ---- O-phase ----
        float cc[2][2];
#pragma unroll
        for (int nq = 0; nq < 2; nq++) {
            cc[nq][0] = sCorr[qw + nq * 8 + c * 2];
            cc[nq][1] = sCorr[qw + nq * 8 + c * 2 + 1];
        }
#pragma unroll
        for (int mi = 0; mi < 2; mi++)
#pragma unroll
            for (int nq = 0; nq < 2; nq++) {
                o[mi][nq][0] *= cc[nq][0];
                o[mi][nq][1] *= cc[nq][1];
                o[mi][nq][2] *= cc[nq][0];
                o[mi][nq][3] *= cc[nq][1];
            }
#pragma unroll
        for (int ks = 0; ks < 8; ks++) {
            int kc = ks * 8 + c;
            uint32_t a[2][4];
#pragma unroll
            for (int mi = 0; mi < 2; mi++) {
                a[mi][0] = sV[(mi * 16 + g)     * SVS + kc];
                a[mi][1] = sV[(mi * 16 + g + 8) * SVS + kc];
                a[mi][2] = sV[(mi * 16 + g)     * SVS + kc + 4];
                a[mi][3] = sV[(mi * 16 + g + 8) * SVS + kc + 4];
            }
#pragma unroll
            for (int nq = 0; nq < 2; nq++) {
                uint32_t b[2];
                b[0] = sP[(ks * 8 + c)     * SPS + qw + nq * 8 + g];
                b[1] = sP[(ks * 8 + c + 4) * SPS + qw + nq * 8 + g];
                mma_tf32(o[0][nq], a[0], b);
                mma_tf32(o[1][nq], a[1], b);
            }
        }
        __syncthreads();
        buf ^= 1;
    }

    // ---- finalize ----
    if (c == 0) {
        sL[qw + g]     = L[0];
        sL[qw + g + 8] = L[1];
    }
    __syncthreads();

    float rl[2][2];
#pragma unroll
    for (int nq = 0; nq < 2; nq++) {
        rl[nq][0] = 1.f / sL[qw + nq * 8 + c * 2];
        rl[nq][1] = 1.f / sL[qw + nq * 8 + c * 2 + 1];
    }
#pragma unroll
    for (int mi = 0; mi < 2; mi++) {
        int d0 = mi * 16 + g;
#pragma unroll
        for (int nq = 0; nq < 2; nq++) {
            int qc = q0 + qw + nq * 8 + c * 2;
            float2 v0 = make_float2(o[mi][nq][0] * rl[nq][0], o[mi][nq][1] * rl[nq][1]);
            float2 v1 = make_float2(o[mi][nq][2] * rl[nq][0], o[mi][nq][3] * rl[nq][1]);
            *(float2*)(msg + (size_t)(d0 * H_ + head) * N_ + qc)       = v0;
            *(float2*)(msg + (size_t)((d0 + 8) * H_ + head) * N_ + qc) = v1;
        }
    }
}

// ---------------------------------------------------------------------------
// InstanceNorm stats.
// ---------------------------------------------------------------------------
__global__ __launch_bounds__(256) void inorm_stats_kernel(const float* __restrict__ Hbuf,
                                                          float* __restrict__ stats)
{
    const int c  = blockIdx.x;
    const int dd = blockIdx.y;
    const float4* row = (const float4*)(Hbuf + ((size_t)dd * C2_ + c) * N_);

    float s = 0.f, ss = 0.f;
    for (int i = threadIdx.x; i < N_ / 4; i += 256) {
        float4 v = row[i];
        s  += v.x + v.y + v.z + v.w;
        ss += v.x * v.x + v.y * v.y + v.z * v.z + v.w * v.w;
    }
    __shared__ float sh_s[8], sh_ss[8];
    for (int off = 16; off > 0; off >>= 1) {
        s  += __shfl_xor_sync(0xffffffffu, s,  off);
        ss += __shfl_xor_sync(0xffffffffu, ss, off);
    }
    int warp = threadIdx.x >> 5, lane = threadIdx.x & 31;
    if (lane == 0) { sh_s[warp] = s; sh_ss[warp] = ss; }
    __syncthreads();
    if (threadIdx.x == 0) {
        float ts = 0.f, tss = 0.f;
        for (int w = 0; w < 8; w++) { ts += sh_s[w]; tss += sh_ss[w]; }
        float mean = ts * (1.f / N_);
        float var  = tss * (1.f / N_) - mean * mean;
        var = fmaxf(var, 0.f);
        stats[((size_t)dd * C2_ + c) * 2 + 0] = mean;
        stats[((size_t)dd * C2_ + c) * 2 + 1] = rsqrtf(var + 1e-5f);
    }
}

__global__ __launch_bounds__(256) void init_kernel(const float* __restrict__ a,
                                                   const float* __restrict__ b,
                                                   float* __restrict__ out)
{
    int i = blockIdx.x * blockDim.x + threadIdx.x;
    const int n4 = D_ * N_ / 4;
    float4* o = (float4*)out;
    if (i < n4)           o[i] = ((const float4*)a)[i];
    else if (i < 2 * n4)  o[i] = ((const float4*)b)[i - n4];
}

// ---------------------------------------------------------------------------
// Host launcher
// ---------------------------------------------------------------------------
extern "C" void kernel_launch(void* const* d_in, const int* in_sizes, int n_in,
                              void* d_out, int out_size)
{
    const float* desc0 = (const float*)d_in[0];
    const float* desc1 = (const float*)d_in[1];
    const float* Wq = (const float*)d_in[2];
    const float* bq = (const float*)d_in[3];
    const float* Wk = (const float*)d_in[4];
    const float* bk = (const float*)d_in[5];
    const float* Wv = (const float*)d_in[6];
    const float* bv = (const float*)d_in[7];
    const float* Wm = (const float*)d_in[8];
    const float* bm = (const float*)d_in[9];
    const float* W1 = (const float*)d_in[10];
    const float* b1 = (const float*)d_in[11];
    const float* W2 = (const float*)d_in[12];
    const float* b2 = (const float*)d_in[13];

    float* x  = (float*)d_out;
    float* x0 = x;
    float* x1 = x + (size_t)D_ * N_;

    float *p_q, *p_k, *p_v, *p_msg, *p_h, *p_stats, *p_wf, *p_bf;
    cudaGetSymbolAddress((void**)&p_q,     g_q);
    cudaGetSymbolAddress((void**)&p_k,     g_k);
    cudaGetSymbolAddress((void**)&p_v,     g_v);
    cudaGetSymbolAddress((void**)&p_msg,   g_msg);
    cudaGetSymbolAddress((void**)&p_h,     g_h);
    cudaGetSymbolAddress((void**)&p_stats, g_stats);
    cudaGetSymbolAddress((void**)&p_wf,    g_wf);
    cudaGetSymbolAddress((void**)&p_bf,    g_bf);

    cudaFuncSetAttribute(attn_mma_kernel,
                         cudaFuncAttributeMaxDynamicSharedMemorySize, ATT_SMEM_BYTES);

    const int BIG = 1 << 30;

    init_kernel<<<512, 256>>>(desc0, desc1, x);
    fuse_w1_kernel<<<L_ * C2_, 128>>>(W1, b1, Wm, bm, p_wf, p_bf);

    for (int l = 0; l < L_; l++) {
        const bool cross = (l & 1);
        const float* s0 = cross ? x1 : x0;
        const float* s1 = cross ? x0 : x1;

        const float* Wq_l = Wq + (size_t)l * D_ * D_;
        const float* bq_l = bq + (size_t)l * D_;
        const float* Wk_l = Wk + (size_t)l * D_ * D_;
        const float* bk_l = bk + (size_t)l * D_;
        const float* Wv_l = Wv + (size_t)l * D_ * D_;
        const float* bv_l = bv + (size_t)l * D_;
        const float* Wf_l = p_wf + (size_t)l * C2_ * C2_;
        const float* bf_l = p_bf + (size_t)l * C2_;
        const float* W2_l = W2 + (size_t)l * D_ * C2_;
        const float* b2_l = b2 + (size_t)l * D_;

        // ---- Q/K/V projections ----
        GemmBatch bqkv{};
        bqkv.j[0] = {Wq_l, bq_l, x0, nullptr, nullptr, p_q,             D_, BIG, 0};
        bqkv.j[1] = {Wq_l, bq_l, x1, nullptr, nullptr, p_q + D_ * N_,   D_, BIG, 0};
        bqkv.j[2] = {Wk_l, bk_l, s0, nullptr, nullptr, p_k,             D_, BIG, 0};
        bqkv.j[3] = {Wk_l, bk_l, s1, nullptr, nullptr, p_k + D_ * N_,   D_, BIG, 0};
        bqkv.j[4] = {Wv_l, bv_l, s0, nullptr, nullptr, p_v,             D_, BIG, 0};
        bqkv.j[5] = {Wv_l, bv_l, s1, nullptr, nullptr, p_v + D_ * N_,   D_, BIG, 0};
        gemm_mma_kernel<128><<<dim3(N_ / 128, D_ / 64, 6), 256>>>(bqkv);

        // ---- attention ----
        attn_mma_kernel<<<dim3(N_ / 128, H_, 2), 256, ATT_SMEM_BYTES>>>(p_q, p_k, p_v, p_msg);

        // ---- MLP layer 1 (msg projection fused into weights) ----
        GemmBatch bmlp1{};
        bmlp1.j[0] = {Wf_l, bf_l, x0, p_msg,           nullptr, p_h,            C2_, D_, 0};
        bmlp1.j[1] = {Wf_l, bf_l, x1, p_msg + D_ * N_, nullptr, p_h + C2_ * N_, C2_, D_, 0};
        gemm_mma_kernel<128><<<dim3(N_ / 128, C2_ / 64, 2), 256>>>(bmlp1);

        // ---- InstanceNorm stats ----
        inorm_stats_kernel<<<dim3(C2_, 2), 256>>>(p_h, p_stats);

        // ---- MLP layer 2 (norm+relu on load) + residual ----
        GemmBatch bmlp2{};
        bmlp2.j[0] = {W2_l, b2_l, p_h,            nullptr, p_stats,           x0, C2_, BIG, 1};
        bmlp2.j[1] = {W2_l, b2_l, p_h + C2_ * N_, nullptr, p_stats + C2_ * 2, x1, C2_, BIG, 1};
        gemm_mma_kernel<64><<<dim3(N_ / 64, D_ / 64, 2), 256>>>(bmlp2);
    }
}

// round 15
// speedup vs baseline: 5.4808x; 1.0394x over previous
#include <cuda_runtime.h>
#include <cstdint>
#include <math.h>

// ---------------------------------------------------------------------------
// SuperGlue-style GNN: L=6 layers, D=128, H=4, DH=32, N=2048, B=1.
// GEMMs + attention on mma.sync tf32. Wm fused into W1 (precomputed).
// ---------------------------------------------------------------------------

#define D_   128
#define N_   2048
#define L_   6
#define H_   4
#define C2_  256

__device__ float g_q   [2 * D_  * N_];
__device__ float g_k   [2 * D_  * N_];
__device__ float g_v   [2 * D_  * N_];
__device__ float g_msg [2 * D_  * N_];
__device__ float g_h   [2 * C2_ * N_];
__device__ float g_stats[2 * C2_ * 2];
__device__ float g_wf  [L_ * C2_ * C2_];   // fused MLP1 weights
__device__ float g_bf  [L_ * C2_];         // fused MLP1 bias

__device__ __forceinline__ uint32_t f2tf32(float x) {
    uint32_t r;
    asm("cvt.rna.tf32.f32 %0, %1;" : "=r"(r) : "f"(x));
    return r;
}

__device__ __forceinline__ void mma_tf32(float* d, const uint32_t* a, const uint32_t* b) {
    asm volatile(
        "mma.sync.aligned.m16n8k8.row.col.f32.tf32.tf32.f32 "
        "{%0,%1,%2,%3}, {%4,%5,%6,%7}, {%8,%9}, {%0,%1,%2,%3};"
        : "+f"(d[0]), "+f"(d[1]), "+f"(d[2]), "+f"(d[3])
        : "r"(a[0]), "r"(a[1]), "r"(a[2]), "r"(a[3]), "r"(b[0]), "r"(b[1]));
}

// ---------------------------------------------------------------------------
// Precompute fused MLP1 weights.
// ---------------------------------------------------------------------------
__global__ __launch_bounds__(128) void fuse_w1_kernel(const float* __restrict__ W1,
                                                      const float* __restrict__ b1,
                                                      const float* __restrict__ Wm,
                                                      const float* __restrict__ bm,
                                                      float* __restrict__ wf,
                                                      float* __restrict__ bf)
{
    const int l = blockIdx.x >> 8;
    const int o = blockIdx.x & 255;
    const int t = threadIdx.x;

    __shared__ float sw[256];
    __shared__ float red[4];

    const float* w1row = W1 + ((size_t)l * C2_ + o) * C2_;
    sw[t]       = w1row[t];
    sw[t + 128] = w1row[t + 128];
    __syncthreads();

    float* out = wf + ((size_t)l * C2_ + o) * C2_;
    out[t] = sw[t];

    const float* wm = Wm + (size_t)l * D_ * D_;
    float acc = 0.f;
#pragma unroll 8
    for (int j = 0; j < 128; j++)
        acc += sw[128 + j] * wm[j * 128 + t];
    out[128 + t] = acc;

    float tb = sw[128 + t] * bm[l * D_ + t];
#pragma unroll
    for (int off = 16; off > 0; off >>= 1)
        tb += __shfl_xor_sync(0xffffffffu, tb, off);
    if ((t & 31) == 0) red[t >> 5] = tb;
    __syncthreads();
    if (t == 0)
        bf[l * C2_ + o] = red[0] + red[1] + red[2] + red[3] + b1[(size_t)l * C2_ + o];
}

// ---------------------------------------------------------------------------
// Batched GEMM (tensor cores), register-staged K pipeline.
// CTA 64(out) x NTILE(n), 8 warps (2 M x 4 N).
// ---------------------------------------------------------------------------
struct GemmJob {
    const float* W;
    const float* bias;
    const float* X0;
    const float* X1;
    const float* stats;
    float*       Y;
    int IN;
    int split;
    int flags;
};
struct GemmBatch { GemmJob j[6]; };

#define SA_STRIDE 36

template<int NTILE>
__global__ __launch_bounds__(256) void gemm_mma_kernel(GemmBatch batch)
{
    constexpr int F4PR = NTILE / 4;
    constexpr int SBS  = NTILE + 8;
    constexpr int NI   = NTILE / 32;
    constexpr int BP   = NTILE / 32;

    GemmJob jb = batch.j[blockIdx.z];
    const int IN = jb.IN;
    const int KT = IN >> 5;
    const int nb = blockIdx.x * NTILE;
    const int ob = blockIdx.y * 64;

    __shared__ uint32_t sA[64 * SA_STRIDE];
    __shared__ uint32_t sB[32 * SBS];

    const int tid  = threadIdx.x;
    const int wid  = tid >> 5;
    const int lane = tid & 31;
    const int g    = lane >> 2;
    const int c    = lane & 3;
    const int wm   = wid & 1;
    const int wn   = wid >> 1;

    float4 wreg[2];
    float4 xreg[BP];
    float2 msreg[BP];

    auto ldg_tiles = [&](int k0) {
#pragma unroll
        for (int p = 0; p < 2; p++) {
            int lin = tid + p * 256;
            int o   = lin >> 3;
            int kq  = lin & 7;
            wreg[p] = *(const float4*)(jb.W + (size_t)(ob + o) * IN + k0 + kq * 4);
        }
#pragma unroll
        for (int p = 0; p < BP; p++) {
            int lin = tid + p * 256;
            int kk  = lin / F4PR;
            int ng  = lin % F4PR;
            int r   = k0 + kk;
            const float* src = (r < jb.split) ? (jb.X0 + (size_t)r * N_)
                                              : (jb.X1 + (size_t)(r - jb.split) * N_);
            xreg[p] = *(const float4*)(src + nb + ng * 4);
            if (jb.stats) msreg[p] = *(const float2*)(jb.stats + 2 * r);
        }
    };
    auto sts_tiles = [&]() {
#pragma unroll
        for (int p = 0; p < 2; p++) {
            int lin = tid + p * 256;
            int o   = lin >> 3;
            int kq  = lin & 7;
            float4 w = wreg[p];
            *(uint4*)&sA[o * SA_STRIDE + kq * 4] =
                make_uint4(f2tf32(w.x), f2tf32(w.y), f2tf32(w.z), f2tf32(w.w));
        }
#pragma unroll
        for (int p = 0; p < BP; p++) {
            int lin = tid + p * 256;
            int kk  = lin / F4PR;
            int ng  = lin % F4PR;
            float4 xv = xreg[p];
            if (jb.stats) {
                float mean = msreg[p].x, rstd = msreg[p].y;
                xv.x = fmaxf(0.f, (xv.x - mean) * rstd);
                xv.y = fmaxf(0.f, (xv.y - mean) * rstd);
                xv.z = fmaxf(0.f, (xv.z - mean) * rstd);
                xv.w = fmaxf(0.f, (xv.w - mean) * rstd);
            }
            *(uint4*)&sB[kk * SBS + ng * 4] =
                make_uint4(f2tf32(xv.x), f2tf32(xv.y), f2tf32(xv.z), f2tf32(xv.w));
        }
    };

    float d[2][NI][4];
#pragma unroll
    for (int mi = 0; mi < 2; mi++)
#pragma unroll
        for (int ni = 0; ni < NI; ni++)
#pragma unroll
            for (int r = 0; r < 4; r++) d[mi][ni][r] = 0.f;

    ldg_tiles(0);
    sts_tiles();
    __syncthreads();

    for (int kt = 0; kt < KT; kt++) {
        const bool have_next = (kt + 1 < KT);
        if (have_next) ldg_tiles((kt + 1) * 32);

#pragma unroll
        for (int ks = 0; ks < 4; ks++) {
            int kc = ks * 8 + c;
            uint32_t a[2][4];
#pragma unroll
            for (int mi = 0; mi < 2; mi++) {
                int row = wm * 32 + mi * 16;
                a[mi][0] = sA[(row + g)     * SA_STRIDE + kc];
                a[mi][1] = sA[(row + g + 8) * SA_STRIDE + kc];
                a[mi][2] = sA[(row + g)     * SA_STRIDE + kc + 4];
                a[mi][3] = sA[(row + g + 8) * SA_STRIDE + kc + 4];
            }
#pragma unroll
            for (int ni = 0; ni < NI; ni++) {
                int col = wn * (NTILE / 4) + ni * 8 + g;
                uint32_t b[2];
                b[0] = sB[(ks * 8 + c)     * SBS + col];
                b[1] = sB[(ks * 8 + c + 4) * SBS + col];
#pragma unroll
                for (int mi = 0; mi < 2; mi++)
                    mma_tf32(d[mi][ni], a[mi], b);
            }
        }
        __syncthreads();
        if (have_next) {
            sts_tiles();
            __syncthreads();
        }
    }

    // ---- epilogue ----
#pragma unroll
    for (int mi = 0; mi < 2; mi++) {
        int orow = ob + wm * 32 + mi * 16 + g;
        float bias0 = jb.bias ? jb.bias[orow]     : 0.f;
        float bias1 = jb.bias ? jb.bias[orow + 8] : 0.f;
        float* y0 = jb.Y + (size_t)orow * N_;
        float* y1 = jb.Y + (size_t)(orow + 8) * N_;
#pragma unroll
        for (int ni = 0; ni < NI; ni++) {
            int ncol = nb + wn * (NTILE / 4) + ni * 8 + c * 2;
            float2 v0 = make_float2(d[mi][ni][0] + bias0, d[mi][ni][1] + bias0);
            float2 v1 = make_float2(d[mi][ni][2] + bias1, d[mi][ni][3] + bias1);
            if (jb.flags & 1) {
                float2 o0 = *(const float2*)(y0 + ncol);
                float2 o1 = *(const float2*)(y1 + ncol);
                v0.x += o0.x; v0.y += o0.y;
                v1.x += o1.x; v1.y += o1.y;
            }
            *(float2*)(y0 + ncol) = v0;
            *(float2*)(y1 + ncol) = v1;
        }
    }
}

// ---------------------------------------------------------------------------
// Flash attention on mma.sync tf32, double-buffered K/V.
// Block: 64 queries x (head, desc); 4 warps (128 thr), 16 q/warp.
// Q fragments hoisted into registers (invariant across key tiles).
// Grid (N/64, H, 2) = 256 blocks; ~70.5 KB smem -> 3 CTAs/SM.
// ---------------------------------------------------------------------------
#define SQ  68
#define SKS 72
#define SVS 68
#define SPS 72
#define KV_WORDS (32 * SKS + 32 * SVS)
#define ATT_SMEM_WORDS (64 * SQ + 2 * KV_WORDS + 64 * SPS + 128)
#define ATT_SMEM_BYTES (ATT_SMEM_WORDS * 4)

__global__ __launch_bounds__(128) void attn_mma_kernel(const float* __restrict__ gq,
                                                       const float* __restrict__ gk,
                                                       const float* __restrict__ gv,
                                                       float* __restrict__ gmsg)
{
    extern __shared__ uint32_t sm[];
    uint32_t* sQT  = sm;                         // [64][SQ]
    uint32_t* sKV  = sQT + 64 * SQ;              // 2 x ([32][SKS] K + [32][SVS] V)
    uint32_t* sP   = sKV + 2 * KV_WORDS;         // [64 keys][SPS] (64 q cols)
    float* sCorr   = (float*)(sP + 64 * SPS);    // [64]
    float* sL      = sCorr + 64;                 // [64]

    const int head = blockIdx.y;
    const int desc = blockIdx.z;
    const size_t base = (size_t)desc * D_ * N_;
    const float* q = gq + base;
    const float* k = gk + base;
    const float* v = gv + base;
    float* msg = gmsg + base;

    const int tid  = threadIdx.x;
    const int wid  = tid >> 5;
    const int lane = tid & 31;
    const int g    = lane >> 2;
    const int c    = lane & 3;
    const int q0   = blockIdx.x * 64;
    const int qw   = wid * 16;

    // ---- load Q^T prescaled (64 q x 32 d) ----
    {
        const float scale = 0.17677669529663687f;
#pragma unroll
        for (int it = 0; it < 4; it++) {
            int lin = tid + it * 128;          // 0..511 float4 slots
            int d   = lin >> 4;                // 0..31
            int q4  = (lin & 15) * 4;          // 0..60
            float4 x = *(const float4*)(q + (size_t)(d * H_ + head) * N_ + q0 + q4);
            sQT[(q4 + 0) * SQ + d] = f2tf32(x.x * scale);
            sQT[(q4 + 1) * SQ + d] = f2tf32(x.y * scale);
            sQT[(q4 + 2) * SQ + d] = f2tf32(x.z * scale);
            sQT[(q4 + 3) * SQ + d] = f2tf32(x.w * scale);
        }
    }
    __syncthreads();

    // ---- hoist Q fragments into registers (invariant over key tiles) ----
    uint32_t aQ[4][4];
#pragma unroll
    for (int ks = 0; ks < 4; ks++) {
        int kc = ks * 8 + c;
        aQ[ks][0] = sQT[(qw + g)     * SQ + kc];
        aQ[ks][1] = sQT[(qw + g + 8) * SQ + kc];
        aQ[ks][2] = sQT[(qw + g)     * SQ + kc + 4];
        aQ[ks][3] = sQT[(qw + g + 8) * SQ + kc + 4];
    }

    float4 kreg[4], vreg[4];
    auto ldg_kv = [&](int mt) {
#pragma unroll
        for (int it = 0; it < 4; it++) {
            int lin = tid + it * 128;
            int d   = lin >> 4;
            int k4  = (lin & 15) * 4;
            size_t gidx = (size_t)(d * H_ + head) * N_ + mt + k4;
            kreg[it] = *(const float4*)(k + gidx);
            vreg[it] = *(const float4*)(v + gidx);
        }
    };
    auto sts_kv = [&](int buf) {
        uint32_t* sK = sKV + buf * KV_WORDS;
        uint32_t* sV = sK + 32 * SKS;
#pragma unroll
        for (int it = 0; it < 4; it++) {
            int lin = tid + it * 128;
            int d   = lin >> 4;
            int k4  = (lin & 15) * 4;
            float4 kk = kreg[it];
            *(uint4*)&sK[d * SKS + k4] =
                make_uint4(f2tf32(kk.x), f2tf32(kk.y), f2tf32(kk.z), f2tf32(kk.w));
            float4 vv = vreg[it];
            *(uint4*)&sV[d * SVS + k4] =
                make_uint4(f2tf32(vv.x), f2tf32(vv.y), f2tf32(vv.z), f2tf32(vv.w));
        }
    };

    float M[2] = {-1e30f, -1e30f};
    float L[2] = {0.f, 0.f};
    float o[2][2][4];
#pragma unroll
    for (int mi = 0; mi < 2; mi++)
#pragma unroll
        for (int nq = 0; nq < 2; nq++)
#pragma unroll
            for (int r = 0; r < 4; r++) o[mi][nq][r] = 0.f;

    ldg_kv(0);
    sts_kv(0);
    __syncthreads();
    int buf = 0;

    for (int mt = 0; mt < N_; mt += 64) {
        const bool have_next = (mt + 64 < N_);
        if (have_next) ldg_kv(mt + 64);

        uint32_t* sK = sKV + buf * KV_WORDS;
        uint32_t* sV = sK + 32 * SKS;

        // ---- S-phase: S[16q x 64k] ----
        float s[8][4];
#pragma unroll
        for (int ni = 0; ni < 8; ni++)
#pragma unroll
            for (int r = 0; r < 4; r++) s[ni][r] = 0.f;
#pragma unroll
        for (int ks = 0; ks < 4; ks++) {
#pragma unroll
            for (int ni = 0; ni < 8; ni++) {
                uint32_t b[2];
                b[0] = sK[(ks * 8 + c)     * SKS + ni * 8 + g];
                b[1] = sK[(ks * 8 + c + 4) * SKS + ni * 8 + g];
                mma_tf32(s[ni], aQ[ks], b);
            }
        }

        if (have_next) sts_kv(buf ^ 1);   // overlapped with softmax

        // ---- online softmax (rows qw+g, qw+g+8) ----
#pragma unroll
        for (int r = 0; r < 2; r++) {
            const int i0 = r * 2;
            float tm = -1e30f;
#pragma unroll
            for (int ni = 0; ni < 8; ni++)
                tm = fmaxf(tm, fmaxf(s[ni][i0], s[ni][i0 + 1]));
            tm = fmaxf(tm, __shfl_xor_sync(0xffffffffu, tm, 1));
            tm = fmaxf(tm, __shfl_xor_sync(0xffffffffu, tm, 2));
            float newM = fmaxf(M[r], tm);
            float corr = __expf(M[r] - newM);
            M[r] = newM;
            float ls = 0.f;
#pragma unroll
            for (int ni = 0; ni < 8; ni++) {
                s[ni][i0]     = __expf(s[ni][i0]     - newM);
                s[ni][i0 + 1] = __expf(s[ni][i0 + 1] - newM);
                ls += s[ni][i0] + s[ni][i0 + 1];
            }
            ls += __shfl_xor_sync(0xffffffffu, ls, 1);
            ls += __shfl_xor_sync(0xffffffffu, ls, 2);
            L[r] = L[r] * corr + ls;
            if (c == 0) sCorr[qw + g + r * 8] = corr;
        }

        // ---- write P -> sP [key][q] ----
#pragma unroll
        for (int ni = 0; ni < 8; ni++) {
            int key = ni * 8 + c * 2;
            sP[(key    ) * SPS + qw + g]     = f2tf32(s[ni][0]);
            sP[(key + 1) * SPS + qw + g]     = f2tf32(s[ni][1]);
            sP[(key    ) * SPS + qw + g + 8] = f2tf32(s[ni][2]);
            sP[(key + 1) * SPS + qw + g + 8] = f2tf32(s[ni][3]);
        }
        __syncthreads();

        // ---- O-phase: O^T[32d x 16q] += V x P ----
        float cc[2][2];
#pragma unroll
        for (int nq = 0; nq < 2; nq++) {
            cc[nq][0] = sCorr[qw + nq * 8 + c * 2];
            cc[nq][1] = sCorr[qw + nq * 8 + c * 2 + 1];
        }
#pragma unroll
        for (int mi = 0; mi < 2; mi++)
#pragma unroll
            for (int nq = 0; nq < 2; nq++) {
                o[mi][nq][0] *= cc[nq][0];
                o[mi][nq][1] *= cc[nq][1];
                o[mi][nq][2] *= cc[nq][0];
                o[mi][nq][3] *= cc[nq][1];
            }
#pragma unroll
        for (int ks = 0; ks < 8; ks++) {
            int kc = ks * 8 + c;
            uint32_t a[2][4];
#pragma unroll
            for (int mi = 0; mi < 2; mi++) {
                a[mi][0] = sV[(mi * 16 + g)     * SVS + kc];
                a[mi][1] = sV[(mi * 16 + g + 8) * SVS + kc];
                a[mi][2] = sV[(mi * 16 + g)     * SVS + kc + 4];
                a[mi][3] = sV[(mi * 16 + g + 8) * SVS + kc + 4];
            }
#pragma unroll
            for (int nq = 0; nq < 2; nq++) {
                uint32_t b[2];
                b[0] = sP[(ks * 8 + c)     * SPS + qw + nq * 8 + g];
                b[1] = sP[(ks * 8 + c + 4) * SPS + qw + nq * 8 + g];
                mma_tf32(o[0][nq], a[0], b);
                mma_tf32(o[1][nq], a[1], b);
            }
        }
        __syncthreads();
        buf ^= 1;
    }

    // ---- finalize ----
    if (c == 0) {
        sL[qw + g]     = L[0];
        sL[qw + g + 8] = L[1];
    }
    __syncthreads();

    float rl[2][2];
#pragma unroll
    for (int nq = 0; nq < 2; nq++) {
        rl[nq][0] = 1.f / sL[qw + nq * 8 + c * 2];
        rl[nq][1] = 1.f / sL[qw + nq * 8 + c * 2 + 1];
    }
#pragma unroll
    for (int mi = 0; mi < 2; mi++) {
        int d0 = mi * 16 + g;
#pragma unroll
        for (int nq = 0; nq < 2; nq++) {
            int qc = q0 + qw + nq * 8 + c * 2;
            float2 v0 = make_float2(o[mi][nq][0] * rl[nq][0], o[mi][nq][1] * rl[nq][1]);
            float2 v1 = make_float2(o[mi][nq][2] * rl[nq][0], o[mi][nq][3] * rl[nq][1]);
            *(float2*)(msg + (size_t)(d0 * H_ + head) * N_ + qc)       = v0;
            *(float2*)(msg + (size_t)((d0 + 8) * H_ + head) * N_ + qc) = v1;
        }
    }
}

// ---------------------------------------------------------------------------
// InstanceNorm stats.
// ---------------------------------------------------------------------------
__global__ __launch_bounds__(256) void inorm_stats_kernel(const float* __restrict__ Hbuf,
                                                          float* __restrict__ stats)
{
    const int c  = blockIdx.x;
    const int dd = blockIdx.y;
    const float4* row = (const float4*)(Hbuf + ((size_t)dd * C2_ + c) * N_);

    float s = 0.f, ss = 0.f;
    for (int i = threadIdx.x; i < N_ / 4; i += 256) {
        float4 v = row[i];
        s  += v.x + v.y + v.z + v.w;
        ss += v.x * v.x + v.y * v.y + v.z * v.z + v.w * v.w;
    }
    __shared__ float sh_s[8], sh_ss[8];
    for (int off = 16; off > 0; off >>= 1) {
        s  += __shfl_xor_sync(0xffffffffu, s,  off);
        ss += __shfl_xor_sync(0xffffffffu, ss, off);
    }
    int warp = threadIdx.x >> 5, lane = threadIdx.x & 31;
    if (lane == 0) { sh_s[warp] = s; sh_ss[warp] = ss; }
    __syncthreads();
    if (threadIdx.x == 0) {
        float ts = 0.f, tss = 0.f;
        for (int w = 0; w < 8; w++) { ts += sh_s[w]; tss += sh_ss[w]; }
        float mean = ts * (1.f / N_);
        float var  = tss * (1.f / N_) - mean * mean;
        var = fmaxf(var, 0.f);
        stats[((size_t)dd * C2_ + c) * 2 + 0] = mean;
        stats[((size_t)dd * C2_ + c) * 2 + 1] = rsqrtf(var + 1e-5f);
    }
}

__global__ __launch_bounds__(256) void init_kernel(const float* __restrict__ a,
                                                   const float* __restrict__ b,
                                                   float* __restrict__ out)
{
    int i = blockIdx.x * blockDim.x + threadIdx.x;
    const int n4 = D_ * N_ / 4;
    float4* o = (float4*)out;
    if (i < n4)           o[i] = ((const float4*)a)[i];
    else if (i < 2 * n4)  o[i] = ((const float4*)b)[i - n4];
}

// ---------------------------------------------------------------------------
// Host launcher
// ---------------------------------------------------------------------------
extern "C" void kernel_launch(void* const* d_in, const int* in_sizes, int n_in,
                              void* d_out, int out_size)
{
    const float* desc0 = (const float*)d_in[0];
    const float* desc1 = (const float*)d_in[1];
    const float* Wq = (const float*)d_in[2];
    const float* bq = (const float*)d_in[3];
    const float* Wk = (const float*)d_in[4];
    const float* bk = (const float*)d_in[5];
    const float* Wv = (const float*)d_in[6];
    const float* bv = (const float*)d_in[7];
    const float* Wm = (const float*)d_in[8];
    const float* bm = (const float*)d_in[9];
    const float* W1 = (const float*)d_in[10];
    const float* b1 = (const float*)d_in[11];
    const float* W2 = (const float*)d_in[12];
    const float* b2 = (const float*)d_in[13];

    float* x  = (float*)d_out;
    float* x0 = x;
    float* x1 = x + (size_t)D_ * N_;

    float *p_q, *p_k, *p_v, *p_msg, *p_h, *p_stats, *p_wf, *p_bf;
    cudaGetSymbolAddress((void**)&p_q,     g_q);
    cudaGetSymbolAddress((void**)&p_k,     g_k);
    cudaGetSymbolAddress((void**)&p_v,     g_v);
    cudaGetSymbolAddress((void**)&p_msg,   g_msg);
    cudaGetSymbolAddress((void**)&p_h,     g_h);
    cudaGetSymbolAddress((void**)&p_stats, g_stats);
    cudaGetSymbolAddress((void**)&p_wf,    g_wf);
    cudaGetSymbolAddress((void**)&p_bf,    g_bf);

    cudaFuncSetAttribute(attn_mma_kernel,
                         cudaFuncAttributeMaxDynamicSharedMemorySize, ATT_SMEM_BYTES);

    const int BIG = 1 << 30;

    init_kernel<<<512, 256>>>(desc0, desc1, x);
    fuse_w1_kernel<<<L_ * C2_, 128>>>(W1, b1, Wm, bm, p_wf, p_bf);

    for (int l = 0; l < L_; l++) {
        const bool cross = (l & 1);
        const float* s0 = cross ? x1 : x0;
        const float* s1 = cross ? x0 : x1;

        const float* Wq_l = Wq + (size_t)l * D_ * D_;
        const float* bq_l = bq + (size_t)l * D_;
        const float* Wk_l = Wk + (size_t)l * D_ * D_;
        const float* bk_l = bk + (size_t)l * D_;
        const float* Wv_l = Wv + (size_t)l * D_ * D_;
        const float* bv_l = bv + (size_t)l * D_;
        const float* Wf_l = p_wf + (size_t)l * C2_ * C2_;
        const float* bf_l = p_bf + (size_t)l * C2_;
        const float* W2_l = W2 + (size_t)l * D_ * C2_;
        const float* b2_l = b2 + (size_t)l * D_;

        // ---- Q/K/V projections ----
        GemmBatch bqkv{};
        bqkv.j[0] = {Wq_l, bq_l, x0, nullptr, nullptr, p_q,             D_, BIG, 0};
        bqkv.j[1] = {Wq_l, bq_l, x1, nullptr, nullptr, p_q + D_ * N_,   D_, BIG, 0};
        bqkv.j[2] = {Wk_l, bk_l, s0, nullptr, nullptr, p_k,             D_, BIG, 0};
        bqkv.j[3] = {Wk_l, bk_l, s1, nullptr, nullptr, p_k + D_ * N_,   D_, BIG, 0};
        bqkv.j[4] = {Wv_l, bv_l, s0, nullptr, nullptr, p_v,             D_, BIG, 0};
        bqkv.j[5] = {Wv_l, bv_l, s1, nullptr, nullptr, p_v + D_ * N_,   D_, BIG, 0};
        gemm_mma_kernel<128><<<dim3(N_ / 128, D_ / 64, 6), 256>>>(bqkv);

        // ---- attention ----
        attn_mma_kernel<<<dim3(N_ / 64, H_, 2), 128, ATT_SMEM_BYTES>>>(p_q, p_k, p_v, p_msg);

        // ---- MLP layer 1 (msg projection fused into weights) ----
        GemmBatch bmlp1{};
        bmlp1.j[0] = {Wf_l, bf_l, x0, p_msg,           nullptr, p_h,            C2_, D_, 0};
        bmlp1.j[1] = {Wf_l, bf_l, x1, p_msg + D_ * N_, nullptr, p_h + C2_ * N_, C2_, D_, 0};
        gemm_mma_kernel<128><<<dim3(N_ / 128, C2_ / 64, 2), 256>>>(bmlp1);

        // ---- InstanceNorm stats ----
        inorm_stats_kernel<<<dim3(C2_, 2), 256>>>(p_h, p_stats);

        // ---- MLP layer 2 (norm+relu on load) + residual ----
        GemmBatch bmlp2{};
        bmlp2.j[0] = {W2_l, b2_l, p_h,            nullptr, p_stats,           x0, C2_, BIG, 1};
        bmlp2.j[1] = {W2_l, b2_l, p_h + C2_ * N_, nullptr, p_stats + C2_ * 2, x1, C2_, BIG, 1};
        gemm_mma_kernel<64><<<dim3(N_ / 64, D_ / 64, 2), 256>>>(bmlp2);
    }
}

// round 17
// speedup vs baseline: 6.4203x; 1.1714x over previous
#include <cuda_runtime.h>
#include <cstdint>
#include <math.h>

// ---------------------------------------------------------------------------
// SuperGlue-style GNN: L=6 layers, D=128, H=4, DH=32, N=2048, B=1.
// GEMMs + attention on mma.sync tf32. Wm fused into W1 (precomputed).
// Attention: cp.async K/V, raw-fp32 tf32 operands, base-2 softmax.
// ---------------------------------------------------------------------------

#define D_   128
#define N_   2048
#define L_   6
#define H_   4
#define C2_  256

__device__ float g_q   [2 * D_  * N_];
__device__ float g_k   [2 * D_  * N_];
__device__ float g_v   [2 * D_  * N_];
__device__ float g_msg [2 * D_  * N_];
__device__ float g_h   [2 * C2_ * N_];
__device__ float g_stats[2 * C2_ * 2];
__device__ float g_wf  [L_ * C2_ * C2_];
__device__ float g_bf  [L_ * C2_];

__device__ __forceinline__ uint32_t f2tf32(float x) {
    uint32_t r;
    asm("cvt.rna.tf32.f32 %0, %1;" : "=r"(r) : "f"(x));
    return r;
}
__device__ __forceinline__ float ex2f(float x) {
    float r;
    asm("ex2.approx.ftz.f32 %0, %1;" : "=f"(r) : "f"(x));
    return r;
}
__device__ __forceinline__ void mma_tf32(float* d, const uint32_t* a, const uint32_t* b) {
    asm volatile(
        "mma.sync.aligned.m16n8k8.row.col.f32.tf32.tf32.f32 "
        "{%0,%1,%2,%3}, {%4,%5,%6,%7}, {%8,%9}, {%0,%1,%2,%3};"
        : "+f"(d[0]), "+f"(d[1]), "+f"(d[2]), "+f"(d[3])
        : "r"(a[0]), "r"(a[1]), "r"(a[2]), "r"(a[3]), "r"(b[0]), "r"(b[1]));
}
__device__ __forceinline__ void cp_async16(uint32_t saddr, const void* gptr) {
    asm volatile("cp.async.cg.shared.global [%0], [%1], 16;" :: "r"(saddr), "l"(gptr));
}
#define CP_COMMIT() asm volatile("cp.async.commit_group;" ::: "memory")
template<int N_PEND>
__device__ __forceinline__ void cp_wait() {
    asm volatile("cp.async.wait_group %0;" :: "n"(N_PEND) : "memory");
}

// ---------------------------------------------------------------------------
// Precompute fused MLP1 weights.
// ---------------------------------------------------------------------------
__global__ __launch_bounds__(128) void fuse_w1_kernel(const float* __restrict__ W1,
                                                      const float* __restrict__ b1,
                                                      const float* __restrict__ Wm,
                                                      const float* __restrict__ bm,
                                                      float* __restrict__ wf,
                                                      float* __restrict__ bf)
{
    const int l = blockIdx.x >> 8;
    const int o = blockIdx.x & 255;
    const int t = threadIdx.x;

    __shared__ float sw[256];
    __shared__ float red[4];

    const float* w1row = W1 + ((size_t)l * C2_ + o) * C2_;
    sw[t]       = w1row[t];
    sw[t + 128] = w1row[t + 128];
    __syncthreads();

    float* out = wf + ((size_t)l * C2_ + o) * C2_;
    out[t] = sw[t];

    const float* wm = Wm + (size_t)l * D_ * D_;
    float acc = 0.f;
#pragma unroll 8
    for (int j = 0; j < 128; j++)
        acc += sw[128 + j] * wm[j * 128 + t];
    out[128 + t] = acc;

    float tb = sw[128 + t] * bm[l * D_ + t];
#pragma unroll
    for (int off = 16; off > 0; off >>= 1)
        tb += __shfl_xor_sync(0xffffffffu, tb, off);
    if ((t & 31) == 0) red[t >> 5] = tb;
    __syncthreads();
    if (t == 0)
        bf[l * C2_ + o] = red[0] + red[1] + red[2] + red[3] + b1[(size_t)l * C2_ + o];
}

// ---------------------------------------------------------------------------
// Batched GEMM (tensor cores), register-staged K pipeline. (unchanged)
// ---------------------------------------------------------------------------
struct GemmJob {
    const float* W;
    const float* bias;
    const float* X0;
    const float* X1;
    const float* stats;
    float*       Y;
    int IN;
    int split;
    int flags;
};
struct GemmBatch { GemmJob j[6]; };

#define SA_STRIDE 36

template<int NTILE>
__global__ __launch_bounds__(256) void gemm_mma_kernel(GemmBatch batch)
{
    constexpr int F4PR = NTILE / 4;
    constexpr int SBS  = NTILE + 8;
    constexpr int NI   = NTILE / 32;
    constexpr int BP   = NTILE / 32;

    GemmJob jb = batch.j[blockIdx.z];
    const int IN = jb.IN;
    const int KT = IN >> 5;
    const int nb = blockIdx.x * NTILE;
    const int ob = blockIdx.y * 64;

    __shared__ uint32_t sA[64 * SA_STRIDE];
    __shared__ uint32_t sB[32 * SBS];

    const int tid  = threadIdx.x;
    const int wid  = tid >> 5;
    const int lane = tid & 31;
    const int g    = lane >> 2;
    const int c    = lane & 3;
    const int wm   = wid & 1;
    const int wn   = wid >> 1;

    float4 wreg[2];
    float4 xreg[BP];
    float2 msreg[BP];

    auto ldg_tiles = [&](int k0) {
#pragma unroll
        for (int p = 0; p < 2; p++) {
            int lin = tid + p * 256;
            int o   = lin >> 3;
            int kq  = lin & 7;
            wreg[p] = *(const float4*)(jb.W + (size_t)(ob + o) * IN + k0 + kq * 4);
        }
#pragma unroll
        for (int p = 0; p < BP; p++) {
            int lin = tid + p * 256;
            int kk  = lin / F4PR;
            int ng  = lin % F4PR;
            int r   = k0 + kk;
            const float* src = (r < jb.split) ? (jb.X0 + (size_t)r * N_)
                                              : (jb.X1 + (size_t)(r - jb.split) * N_);
            xreg[p] = *(const float4*)(src + nb + ng * 4);
            if (jb.stats) msreg[p] = *(const float2*)(jb.stats + 2 * r);
        }
    };
    auto sts_tiles = [&]() {
#pragma unroll
        for (int p = 0; p < 2; p++) {
            int lin = tid + p * 256;
            int o   = lin >> 3;
            int kq  = lin & 7;
            float4 w = wreg[p];
            *(uint4*)&sA[o * SA_STRIDE + kq * 4] =
                make_uint4(f2tf32(w.x), f2tf32(w.y), f2tf32(w.z), f2tf32(w.w));
        }
#pragma unroll
        for (int p = 0; p < BP; p++) {
            int lin = tid + p * 256;
            int kk  = lin / F4PR;
            int ng  = lin % F4PR;
            float4 xv = xreg[p];
            if (jb.stats) {
                float mean = msreg[p].x, rstd = msreg[p].y;
                xv.x = fmaxf(0.f, (xv.x - mean) * rstd);
                xv.y = fmaxf(0.f, (xv.y - mean) * rstd);
                xv.z = fmaxf(0.f, (xv.z - mean) * rstd);
                xv.w = fmaxf(0.f, (xv.w - mean) * rstd);
            }
            *(uint4*)&sB[kk * SBS + ng * 4] =
                make_uint4(f2tf32(xv.x), f2tf32(xv.y), f2tf32(xv.z), f2tf32(xv.w));
        }
    };

    float d[2][NI][4];
#pragma unroll
    for (int mi = 0; mi < 2; mi++)
#pragma unroll
        for (int ni = 0; ni < NI; ni++)
#pragma unroll
            for (int r = 0; r < 4; r++) d[mi][ni][r] = 0.f;

    ldg_tiles(0);
    sts_tiles();
    __syncthreads();

    for (int kt = 0; kt < KT; kt++) {
        const bool have_next = (kt + 1 < KT);
        if (have_next) ldg_tiles((kt + 1) * 32);

#pragma unroll
        for (int ks = 0; ks < 4; ks++) {
            int kc = ks * 8 + c;
            uint32_t a[2][4];
#pragma unroll
            for (int mi = 0; mi < 2; mi++) {
                int row = wm * 32 + mi * 16;
                a[mi][0] = sA[(row + g)     * SA_STRIDE + kc];
                a[mi][1] = sA[(row + g + 8) * SA_STRIDE + kc];
                a[mi][2] = sA[(row + g)     * SA_STRIDE + kc + 4];
                a[mi][3] = sA[(row + g + 8) * SA_STRIDE + kc + 4];
            }
#pragma unroll
            for (int ni = 0; ni < NI; ni++) {
                int col = wn * (NTILE / 4) + ni * 8 + g;
                uint32_t b[2];
                b[0] = sB[(ks * 8 + c)     * SBS + col];
                b[1] = sB[(ks * 8 + c + 4) * SBS + col];
#pragma unroll
                for (int mi = 0; mi < 2; mi++)
                    mma_tf32(d[mi][ni], a[mi], b);
            }
        }
        __syncthreads();
        if (have_next) {
            sts_tiles();
            __syncthreads();
        }
    }

#pragma unroll
    for (int mi = 0; mi < 2; mi++) {
        int orow = ob + wm * 32 + mi * 16 + g;
        float bias0 = jb.bias ? jb.bias[orow]     : 0.f;
        float bias1 = jb.bias ? jb.bias[orow + 8] : 0.f;
        float* y0 = jb.Y + (size_t)orow * N_;
        float* y1 = jb.Y + (size_t)(orow + 8) * N_;
#pragma unroll
        for (int ni = 0; ni < NI; ni++) {
            int ncol = nb + wn * (NTILE / 4) + ni * 8 + c * 2;
            float2 v0 = make_float2(d[mi][ni][0] + bias0, d[mi][ni][1] + bias0);
            float2 v1 = make_float2(d[mi][ni][2] + bias1, d[mi][ni][3] + bias1);
            if (jb.flags & 1) {
                float2 o0 = *(const float2*)(y0 + ncol);
                float2 o1 = *(const float2*)(y1 + ncol);
                v0.x += o0.x; v0.y += o0.y;
                v1.x += o1.x; v1.y += o1.y;
            }
            *(float2*)(y0 + ncol) = v0;
            *(float2*)(y1 + ncol) = v1;
        }
    }
}

// ---------------------------------------------------------------------------
// Flash attention, mma.sync tf32. cp.async double-buffered K/V (raw fp32 bits
// as tf32 operands — HW truncates mantissa), base-2 softmax (ex2.approx).
// Block: 64 queries x (head, desc); 4 warps. Grid (N/64, H, 2) = 256.
// ---------------------------------------------------------------------------
#define SQ  68
#define SKS 72
#define SVS 68
#define SPS 72
#define KV_WORDS (32 * SKS + 32 * SVS)
#define ATT_SMEM_WORDS (64 * SQ + 2 * KV_WORDS + 64 * SPS + 128)
#define ATT_SMEM_BYTES (ATT_SMEM_WORDS * 4)

__global__ __launch_bounds__(128, 3) void attn_mma_kernel(const float* __restrict__ gq,
                                                          const float* __restrict__ gk,
                                                          const float* __restrict__ gv,
                                                          float* __restrict__ gmsg)
{
    extern __shared__ uint32_t sm[];
    uint32_t* sQT  = sm;                         // [64][SQ]
    uint32_t* sKV  = sQT + 64 * SQ;              // 2 x ([32][SKS] K + [32][SVS] V)
    uint32_t* sP   = sKV + 2 * KV_WORDS;         // [64 keys][SPS]
    float* sCorr   = (float*)(sP + 64 * SPS);    // [64]
    float* sL      = sCorr + 64;                 // [64]

    const uint32_t smem_u32 = (uint32_t)__cvta_generic_to_shared(sm);

    const int head = blockIdx.y;
    const int desc = blockIdx.z;
    const size_t base = (size_t)desc * D_ * N_;
    const float* q = gq + base;
    const float* k = gk + base;
    const float* v = gv + base;
    float* msg = gmsg + base;

    const int tid  = threadIdx.x;
    const int wid  = tid >> 5;
    const int lane = tid & 31;
    const int g    = lane >> 2;
    const int c    = lane & 3;
    const int q0   = blockIdx.x * 64;
    const int qw   = wid * 16;

    // ---- issue K/V tile 0 fetch first (overlaps with Q prep) ----
    auto cp_kv = [&](int mt, int buf) {
        uint32_t sKa = smem_u32 + (uint32_t)(64 * SQ + buf * KV_WORDS) * 4;
        uint32_t sVa = sKa + 32 * SKS * 4;
#pragma unroll
        for (int it = 0; it < 4; it++) {
            int lin = tid + it * 128;
            int d   = lin >> 4;
            int k4  = (lin & 15) * 4;
            size_t gidx = (size_t)(d * H_ + head) * N_ + mt + k4;
            cp_async16(sKa + (uint32_t)(d * SKS + k4) * 4, k + gidx);
            cp_async16(sVa + (uint32_t)(d * SVS + k4) * 4, v + gidx);
        }
        CP_COMMIT();
    };
    cp_kv(0, 0);

    // ---- load Q^T prescaled by log2(e)/sqrt(32) (base-2 softmax) ----
    {
        const float scale = 0.17677669529663687f * 1.4426950408889634f;
#pragma unroll
        for (int it = 0; it < 4; it++) {
            int lin = tid + it * 128;
            int d   = lin >> 4;
            int q4  = (lin & 15) * 4;
            float4 x = *(const float4*)(q + (size_t)(d * H_ + head) * N_ + q0 + q4);
            sQT[(q4 + 0) * SQ + d] = f2tf32(x.x * scale);
            sQT[(q4 + 1) * SQ + d] = f2tf32(x.y * scale);
            sQT[(q4 + 2) * SQ + d] = f2tf32(x.z * scale);
            sQT[(q4 + 3) * SQ + d] = f2tf32(x.w * scale);
        }
    }
    __syncthreads();

    // ---- hoist Q fragments (invariant across key tiles) ----
    uint32_t aQ[4][4];
#pragma unroll
    for (int ks = 0; ks < 4; ks++) {
        int kc = ks * 8 + c;
        aQ[ks][0] = sQT[(qw + g)     * SQ + kc];
        aQ[ks][1] = sQT[(qw + g + 8) * SQ + kc];
        aQ[ks][2] = sQT[(qw + g)     * SQ + kc + 4];
        aQ[ks][3] = sQT[(qw + g + 8) * SQ + kc + 4];
    }

    float M[2] = {-1e30f, -1e30f};
    float L[2] = {0.f, 0.f};
    float o[2][2][4];
#pragma unroll
    for (int mi = 0; mi < 2; mi++)
#pragma unroll
        for (int nq = 0; nq < 2; nq++)
#pragma unroll
            for (int r = 0; r < 4; r++) o[mi][nq][r] = 0.f;

    int buf = 0;
    for (int mt = 0; mt < N_; mt += 64) {
        const bool have_next = (mt + 64 < N_);
        if (have_next) {
            cp_kv(mt + 64, buf ^ 1);
            cp_wait<1>();
        } else {
            cp_wait<0>();
        }
        __syncthreads();

        uint32_t* sK = sKV + buf * KV_WORDS;
        uint32_t* sV = sK + 32 * SKS;

        // ---- S-phase: S[16q x 64k] ----
        float s[8][4];
#pragma unroll
        for (int ni = 0; ni < 8; ni++)
#pragma unroll
            for (int r = 0; r < 4; r++) s[ni][r] = 0.f;
#pragma unroll
        for (int ks = 0; ks < 4; ks++) {
#pragma unroll
            for (int ni = 0; ni < 8; ni++) {
                uint32_t b[2];
                b[0] = sK[(ks * 8 + c)     * SKS + ni * 8 + g];
                b[1] = sK[(ks * 8 + c + 4) * SKS + ni * 8 + g];
                mma_tf32(s[ni], aQ[ks], b);
            }
        }

        // ---- online softmax, base 2 (rows qw+g, qw+g+8) ----
#pragma unroll
        for (int r = 0; r < 2; r++) {
            const int i0 = r * 2;
            float tm = -1e30f;
#pragma unroll
            for (int ni = 0; ni < 8; ni++)
                tm = fmaxf(tm, fmaxf(s[ni][i0], s[ni][i0 + 1]));
            tm = fmaxf(tm, __shfl_xor_sync(0xffffffffu, tm, 1));
            tm = fmaxf(tm, __shfl_xor_sync(0xffffffffu, tm, 2));
            float newM = fmaxf(M[r], tm);
            float corr = ex2f(M[r] - newM);
            M[r] = newM;
            float ls = 0.f;
#pragma unroll
            for (int ni = 0; ni < 8; ni++) {
                s[ni][i0]     = ex2f(s[ni][i0]     - newM);
                s[ni][i0 + 1] = ex2f(s[ni][i0 + 1] - newM);
                ls += s[ni][i0] + s[ni][i0 + 1];
            }
            ls += __shfl_xor_sync(0xffffffffu, ls, 1);
            ls += __shfl_xor_sync(0xffffffffu, ls, 2);
            L[r] = L[r] * corr + ls;
            if (c == 0) sCorr[qw + g + r * 8] = corr;
        }

        // ---- write P (raw fp32 bits; mma truncates to tf32) ----
#pragma unroll
        for (int ni = 0; ni < 8; ni++) {
            int key = ni * 8 + c * 2;
            sP[(key    ) * SPS + qw + g]     = __float_as_uint(s[ni][0]);
            sP[(key + 1) * SPS + qw + g]     = __float_as_uint(s[ni][1]);
            sP[(key    ) * SPS + qw + g + 8] = __float_as_uint(s[ni][2]);
            sP[(key + 1) * SPS + qw + g + 8] = __float_as_uint(s[ni][3]);
        }
        __syncthreads();

        // ---- O-phase: O^T[32d x 16q] += V x P ----
        float cc[2][2];
#pragma unroll
        for (int nq = 0; nq < 2; nq++) {
            cc[nq][0] = sCorr[qw + nq * 8 + c * 2];
            cc[nq][1] = sCorr[qw + nq * 8 + c * 2 + 1];
        }
#pragma unroll
        for (int mi = 0; mi < 2; mi++)
#pragma unroll
            for (int nq = 0; nq < 2; nq++) {
                o[mi][nq][0] *= cc[nq][0];
                o[mi][nq][1] *= cc[nq][1];
                o[mi][nq][2] *= cc[nq][0];
                o[mi][nq][3] *= cc[nq][1];
            }
#pragma unroll
        for (int ks = 0; ks < 8; ks++) {
            int kc = ks * 8 + c;
            uint32_t a[2][4];
#pragma unroll
            for (int mi = 0; mi < 2; mi++) {
                a[mi][0] = sV[(mi * 16 + g)     * SVS + kc];
                a[mi][1] = sV[(mi * 16 + g + 8) * SVS + kc];
                a[mi][2] = sV[(mi * 16 + g)     * SVS + kc + 4];
                a[mi][3] = sV[(mi * 16 + g + 8) * SVS + kc + 4];
            }
#pragma unroll
            for (int nq = 0; nq < 2; nq++) {
                uint32_t b[2];
                b[0] = sP[(ks * 8 + c)     * SPS + qw + nq * 8 + g];
                b[1] = sP[(ks * 8 + c + 4) * SPS + qw + nq * 8 + g];
                mma_tf32(o[0][nq], a[0], b);
                mma_tf32(o[1][nq], a[1], b);
            }
        }
        __syncthreads();
        buf ^= 1;
    }

    // ---- finalize ----
    if (c == 0) {
        sL[qw + g]     = L[0];
        sL[qw + g + 8] = L[1];
    }
    __syncthreads();

    float rl[2][2];
#pragma unroll
    for (int nq = 0; nq < 2; nq++) {
        rl[nq][0] = 1.f / sL[qw + nq * 8 + c * 2];
        rl[nq][1] = 1.f / sL[qw + nq * 8 + c * 2 + 1];
    }
#pragma unroll
    for (int mi = 0; mi < 2; mi++) {
        int d0 = mi * 16 + g;
#pragma unroll
        for (int nq = 0; nq < 2; nq++) {
            int qc = q0 + qw + nq * 8 + c * 2;
            float2 v0 = make_float2(o[mi][nq][0] * rl[nq][0], o[mi][nq][1] * rl[nq][1]);
            float2 v1 = make_float2(o[mi][nq][2] * rl[nq][0], o[mi][nq][3] * rl[nq][1]);
            *(float2*)(msg + (size_t)(d0 * H_ + head) * N_ + qc)       = v0;
            *(float2*)(msg + (size_t)((d0 + 8) * H_ + head) * N_ + qc) = v1;
        }
    }
}

// ---------------------------------------------------------------------------
// InstanceNorm stats.
// ---------------------------------------------------------------------------
__global__ __launch_bounds__(256) void inorm_stats_kernel(const float* __restrict__ Hbuf,
                                                          float* __restrict__ stats)
{
    const int c  = blockIdx.x;
    const int dd = blockIdx.y;
    const float4* row = (const float4*)(Hbuf + ((size_t)dd * C2_ + c) * N_);

    float s = 0.f, ss = 0.f;
    for (int i = threadIdx.x; i < N_ / 4; i += 256) {
        float4 v = row[i];
        s  += v.x + v.y + v.z + v.w;
        ss += v.x * v.x + v.y * v.y + v.z * v.z + v.w * v.w;
    }
    __shared__ float sh_s[8], sh_ss[8];
    for (int off = 16; off > 0; off >>= 1) {
        s  += __shfl_xor_sync(0xffffffffu, s,  off);
        ss += __shfl_xor_sync(0xffffffffu, ss, off);
    }
    int warp = threadIdx.x >> 5, lane = threadIdx.x & 31;
    if (lane == 0) { sh_s[warp] = s; sh_ss[warp] = ss; }
    __syncthreads();
    if (threadIdx.x == 0) {
        float ts = 0.f, tss = 0.f;
        for (int w = 0; w < 8; w++) { ts += sh_s[w]; tss += sh_ss[w]; }
        float mean = ts * (1.f / N_);
        float var  = tss * (1.f / N_) - mean * mean;
        var = fmaxf(var, 0.f);
        stats[((size_t)dd * C2_ + c) * 2 + 0] = mean;
        stats[((size_t)dd * C2_ + c) * 2 + 1] = rsqrtf(var + 1e-5f);
    }
}

__global__ __launch_bounds__(256) void init_kernel(const float* __restrict__ a,
                                                   const float* __restrict__ b,
                                                   float* __restrict__ out)
{
    int i = blockIdx.x * blockDim.x + threadIdx.x;
    const int n4 = D_ * N_ / 4;
    float4* o = (float4*)out;
    if (i < n4)           o[i] = ((const float4*)a)[i];
    else if (i < 2 * n4)  o[i] = ((const float4*)b)[i - n4];
}

// ---------------------------------------------------------------------------
// Host launcher
// ---------------------------------------------------------------------------
extern "C" void kernel_launch(void* const* d_in, const int* in_sizes, int n_in,
                              void* d_out, int out_size)
{
    const float* desc0 = (const float*)d_in[0];
    const float* desc1 = (const float*)d_in[1];
    const float* Wq = (const float*)d_in[2];
    const float* bq = (const float*)d_in[3];
    const float* Wk = (const float*)d_in[4];
    const float* bk = (const float*)d_in[5];
    const float* Wv = (const float*)d_in[6];
    const float* bv = (const float*)d_in[7];
    const float* Wm = (const float*)d_in[8];
    const float* bm = (const float*)d_in[9];
    const float* W1 = (const float*)d_in[10];
    const float* b1 = (const float*)d_in[11];
    const float* W2 = (const float*)d_in[12];
    const float* b2 = (const float*)d_in[13];

    float* x  = (float*)d_out;
    float* x0 = x;
    float* x1 = x + (size_t)D_ * N_;

    float *p_q, *p_k, *p_v, *p_msg, *p_h, *p_stats, *p_wf, *p_bf;
    cudaGetSymbolAddress((void**)&p_q,     g_q);
    cudaGetSymbolAddress((void**)&p_k,     g_k);
    cudaGetSymbolAddress((void**)&p_v,     g_v);
    cudaGetSymbolAddress((void**)&p_msg,   g_msg);
    cudaGetSymbolAddress((void**)&p_h,     g_h);
    cudaGetSymbolAddress((void**)&p_stats, g_stats);
    cudaGetSymbolAddress((void**)&p_wf,    g_wf);
    cudaGetSymbolAddress((void**)&p_bf,    g_bf);

    cudaFuncSetAttribute(attn_mma_kernel,
                         cudaFuncAttributeMaxDynamicSharedMemorySize, ATT_SMEM_BYTES);

    const int BIG = 1 << 30;

    init_kernel<<<512, 256>>>(desc0, desc1, x);
    fuse_w1_kernel<<<L_ * C2_, 128>>>(W1, b1, Wm, bm, p_wf, p_bf);

    for (int l = 0; l < L_; l++) {
        const bool cross = (l & 1);
        const float* s0 = cross ? x1 : x0;
        const float* s1 = cross ? x0 : x1;

        const float* Wq_l = Wq + (size_t)l * D_ * D_;
        const float* bq_l = bq + (size_t)l * D_;
        const float* Wk_l = Wk + (size_t)l * D_ * D_;
        const float* bk_l = bk + (size_t)l * D_;
        const float* Wv_l = Wv + (size_t)l * D_ * D_;
        const float* bv_l = bv + (size_t)l * D_;
        const float* Wf_l = p_wf + (size_t)l * C2_ * C2_;
        const float* bf_l = p_bf + (size_t)l * C2_;
        const float* W2_l = W2 + (size_t)l * D_ * C2_;
        const float* b2_l = b2 + (size_t)l * D_;

        // ---- Q/K/V projections ----
        GemmBatch bqkv{};
        bqkv.j[0] = {Wq_l, bq_l, x0, nullptr, nullptr, p_q,             D_, BIG, 0};
        bqkv.j[1] = {Wq_l, bq_l, x1, nullptr, nullptr, p_q + D_ * N_,   D_, BIG, 0};
        bqkv.j[2] = {Wk_l, bk_l, s0, nullptr, nullptr, p_k,             D_, BIG, 0};
        bqkv.j[3] = {Wk_l, bk_l, s1, nullptr, nullptr, p_k + D_ * N_,   D_, BIG, 0};
        bqkv.j[4] = {Wv_l, bv_l, s0, nullptr, nullptr, p_v,             D_, BIG, 0};
        bqkv.j[5] = {Wv_l, bv_l, s1, nullptr, nullptr, p_v + D_ * N_,   D_, BIG, 0};
        gemm_mma_kernel<128><<<dim3(N_ / 128, D_ / 64, 6), 256>>>(bqkv);

        // ---- attention ----
        attn_mma_kernel<<<dim3(N_ / 64, H_, 2), 128, ATT_SMEM_BYTES>>>(p_q, p_k, p_v, p_msg);

        // ---- MLP layer 1 (msg projection fused into weights) ----
        GemmBatch bmlp1{};
        bmlp1.j[0] = {Wf_l, bf_l, x0, p_msg,           nullptr, p_h,            C2_, D_, 0};
        bmlp1.j[1] = {Wf_l, bf_l, x1, p_msg + D_ * N_, nullptr, p_h + C2_ * N_, C2_, D_, 0};
        gemm_mma_kernel<128><<<dim3(N_ / 128, C2_ / 64, 2), 256>>>(bmlp1);

        // ---- InstanceNorm stats ----
        inorm_stats_kernel<<<dim3(C2_, 2), 256>>>(p_h, p_stats);

        // ---- MLP layer 2 (norm+relu on load) + residual ----
        GemmBatch bmlp2{};
        bmlp2.j[0] = {W2_l, b2_l, p_h,            nullptr, p_stats,           x0, C2_, BIG, 1};
        bmlp2.j[1] = {W2_l, b2_l, p_h + C2_ * N_, nullptr, p_stats + C2_ * 2, x1, C2_, BIG, 1};
        gemm_mma_kernel<64><<<dim3(N_ / 64, D_ / 64, 2), 256>>>(bmlp2);
    }
}